// round 12
// baseline (speedup 1.0000x reference)
#include <cuda_runtime.h>
#include <cuda_bf16.h>
#include <math.h>
#include <stdint.h>

#define NBATCH 32
#define NHEAD  8
#define SEQ    512
#define HD     64

constexpr size_t V_SIZE   = (size_t)NBATCH * SEQ * NHEAD * HD;     // 8388608
constexpr size_t SER_SIZE = (size_t)NBATCH * NHEAD * SEQ * SEQ;    // 67108864

// ---- prepacked tf32 fragment arrays (fragment-major, rna-rounded fp32 bits) ----
// KB idx = bh*8192 + st*128 + kt*32 + lane   (uint4 each)
// VB idx = bh*8192 + dt*1024 + st*32 + lane  (uint4 each)
// QA: [bh][rtile 32][kt 4][lane 32] {uint4 kstep0, uint4 kstep1}
__device__ uint32_t d_KB[(size_t)256 * 64 * 4 * 32 * 4];
__device__ uint32_t d_VB[(size_t)256 * 8 * 32 * 32 * 4];
__device__ uint32_t d_QA[(size_t)256 * 32 * 4 * 32 * 8];

constexpr int KBN = 256 * 64 * 4 * 32;
constexpr int VBN = 256 * 8 * 32 * 32;
constexpr int QAN = 256 * 32 * 4 * 32;
constexpr int PREN = KBN + VBN + QAN;

// ---- smem layout (bytes): stash only (A region deleted) ----
constexpr uint32_t STASH_W = 4352;          // per-warp fp32 P stash [16][68]
constexpr uint32_t RS_OFF  = 8 * STASH_W;   // 34816
constexpr uint32_t INV_OFF = RS_OFF + 512;  // 35328
constexpr uint32_t SMEM_BYTES = INV_OFF + 64;  // 35392

// round-to-nearest tf32 (rna; truncation would bias dot products)
__device__ __forceinline__ uint32_t rna(float x) {
    uint32_t r;
    asm("cvt.rna.tf32.f32 %0, %1;" : "=r"(r) : "f"(x));
    return r;
}

__device__ __forceinline__ void mma_tf32(float* c, const uint32_t* a, uint32_t b0, uint32_t b1) {
    asm volatile(
        "mma.sync.aligned.m16n8k8.row.col.f32.tf32.tf32.f32 "
        "{%0,%1,%2,%3},{%4,%5,%6,%7},{%8,%9},{%0,%1,%2,%3};\n"
        : "+f"(c[0]), "+f"(c[1]), "+f"(c[2]), "+f"(c[3])
        : "r"(a[0]), "r"(a[1]), "r"(a[2]), "r"(a[3]), "r"(b0), "r"(b1));
}

// ---------------- prepack (unchanged from round 10/11) ----------------
__global__ void __launch_bounds__(256) prepack(const float* __restrict__ Q,
                                               const float* __restrict__ K,
                                               const float* __restrict__ V) {
    int idx = blockIdx.x * 256 + threadIdx.x;
    int g = (idx >> 2) & 7, t = idx & 3;
    if (idx < KBN) {
        int kt = (idx >> 5) & 3, st = (idx >> 7) & 63, bh = idx >> 13;
        int b = bh >> 3, h = bh & 7;
        int s = st * 8 + g, k0 = kt * 16 + t;
        const float* kp = K + (((size_t)b * SEQ + s) * NHEAD + h) * HD;
        *(uint4*)(d_KB + (size_t)idx * 4) =
            make_uint4(rna(kp[k0]), rna(kp[k0 + 4]), rna(kp[k0 + 8]), rna(kp[k0 + 12]));
    } else if (idx < KBN + VBN) {
        int i = idx - KBN;
        int st = (i >> 5) & 31, dt = (i >> 10) & 7, bh = i >> 13;
        int b = bh >> 3, h = bh & 7;
        int d = dt * 8 + g, ks = st * 16 + t;
        const float* vp = V + ((size_t)b * SEQ * NHEAD + h) * HD + d;
        *(uint4*)(d_VB + (size_t)i * 4) =
            make_uint4(rna(vp[(size_t)ks * 512]),       rna(vp[(size_t)(ks + 4) * 512]),
                       rna(vp[(size_t)(ks + 8) * 512]), rna(vp[(size_t)(ks + 12) * 512]));
    } else if (idx < PREN) {
        int i = idx - KBN - VBN;
        int kt = (i >> 5) & 3, rt = (i >> 7) & 31, bh = i >> 12;
        int b = bh >> 3, h = bh & 7;
        int k0 = kt * 16 + t;
        const float* qp = Q + (((size_t)b * SEQ + rt * 16) * NHEAD + h) * HD;
        *(uint4*)(d_QA + (size_t)i * 8) =
            make_uint4(rna(qp[(size_t)g * 512 + k0]),     rna(qp[(size_t)(g + 8) * 512 + k0]),
                       rna(qp[(size_t)g * 512 + k0 + 4]), rna(qp[(size_t)(g + 8) * 512 + k0 + 4]));
        *(uint4*)(d_QA + (size_t)i * 8 + 4) =
            make_uint4(rna(qp[(size_t)g * 512 + k0 + 8]),  rna(qp[(size_t)(g + 8) * 512 + k0 + 8]),
                       rna(qp[(size_t)g * 512 + k0 + 12]), rna(qp[(size_t)(g + 8) * 512 + k0 + 12]));
    }
}

// ---------------- main ----------------
// CTA: 16 rows x 512 cols. 8 warps = 8 col-slices of 64.
// B operands loaded DIRECTLY gmem->reg (LDG.128, L2-resident) with 2-deep
// register double-buffering; no cp.async, no smem staging.
__global__ void __launch_bounds__(256, 2) anomaly_mma(const float* __restrict__ SG,
                                                      float* __restrict__ out) {
    extern __shared__ char sm[];
    float* RS  = (float*)(sm + RS_OFF);
    float* INV = (float*)(sm + INV_OFF);

    const int tid = threadIdx.x, lane = tid & 31, wid = tid >> 5;
    const int g = lane >> 2, t = lane & 3;
    const int mt = blockIdx.x & 31;
    const int bh = blockIdx.x >> 5;
    const int h = bh & 7, b = bh >> 3;
    const int l0 = mt * 16;
    const int cq = wid;

    float* stg = (float*)(sm + wid * STASH_W);

    // per-warp fragment base pointers (lane folded in; all LDG.128 coalesced)
    const uint4* kbase = (const uint4*)d_KB + (size_t)bh * 8192 + (size_t)(cq * 8) * 128 + lane;
    const uint4* vbase = (const uint4*)d_VB + (size_t)bh * 8192 + (size_t)(cq * 4) * 32 + lane;

    // ---- Q fragments (tf32) ----
    uint32_t qf[4][8];
    {
        const uint32_t* qa = d_QA + ((size_t)bh * 32 + mt) * 1024 + (size_t)lane * 8;
        #pragma unroll
        for (int kt = 0; kt < 4; kt++) {
            uint4 X = *(const uint4*)(qa + kt * 256);
            uint4 Y = *(const uint4*)(qa + kt * 256 + 4);
            qf[kt][0] = X.x; qf[kt][1] = X.y; qf[kt][2] = X.z; qf[kt][3] = X.w;
            qf[kt][4] = Y.x; qf[kt][5] = Y.y; qf[kt][6] = Y.z; qf[kt][7] = Y.w;
        }
    }

    // ================= loop1: GEMM1 (tf32) -> exp -> fp32 stash =================
    // stream stiles st=0..7 (per warp), register double-buffer of 4 uint4
    uint4 Kb[2][4];
    #pragma unroll
    for (int kt = 0; kt < 4; kt++) Kb[0][kt] = kbase[0 * 128 + kt * 32];

    float rs0 = 0.f, rs1 = 0.f;
    #pragma unroll
    for (int k2 = 0; k2 < 4; k2++) {
        float aA[2][4], aB[2][4];
        #pragma unroll
        for (int n = 0; n < 2; n++)
            #pragma unroll
            for (int r = 0; r < 4; r++) { aA[n][r] = 0.f; aB[n][r] = 0.f; }

        #pragma unroll
        for (int n = 0; n < 2; n++) {
            const int stn = 2 * k2 + n;
            if (stn < 7) {
                #pragma unroll
                for (int kt = 0; kt < 4; kt++)
                    Kb[(stn + 1) & 1][kt] = kbase[(stn + 1) * 128 + kt * 32];
            }
            const uint4* Bv = Kb[stn & 1];
            #pragma unroll
            for (int kt = 0; kt < 4; kt++) {
                float* acc = (kt & 1) ? aB[n] : aA[n];
                mma_tf32(acc, &qf[kt][0], Bv[kt].x, Bv[kt].y);
                mma_tf32(acc, &qf[kt][4], Bv[kt].z, Bv[kt].w);
            }
        }

        float p[2][4];
        #pragma unroll
        for (int n = 0; n < 2; n++)
            #pragma unroll
            for (int r = 0; r < 4; r++)
                p[n][r] = __expf(0.125f * (aA[n][r] + aB[n][r]));

        rs0 += p[0][0] + p[0][1] + p[1][0] + p[1][1];
        rs1 += p[0][2] + p[0][3] + p[1][2] + p[1][3];

        #pragma unroll
        for (int n = 0; n < 2; n++) {
            const int col = k2 * 16 + n * 8 + 2 * t;
            *(float2*)&stg[g * 68 + col]       = make_float2(p[n][0], p[n][1]);
            *(float2*)&stg[(g + 8) * 68 + col] = make_float2(p[n][2], p[n][3]);
        }
    }

    // ---- V first-group register prefetch: overlaps rowsum barrier phase ----
    uint4 Vb[2][4];
    #pragma unroll
    for (int j = 0; j < 4; j++) Vb[0][j] = vbase[(size_t)j * 1024 + 0 * 32];

    // ---- rowsums -> inv ----
    rs0 += __shfl_xor_sync(0xffffffffu, rs0, 1);
    rs0 += __shfl_xor_sync(0xffffffffu, rs0, 2);
    rs1 += __shfl_xor_sync(0xffffffffu, rs1, 1);
    rs1 += __shfl_xor_sync(0xffffffffu, rs1, 2);
    if (t == 0) {
        RS[g * 8 + wid]       = rs0;
        RS[(g + 8) * 8 + wid] = rs1;
    }
    __syncthreads();
    if (tid < 16) {
        float s = 0.f;
        #pragma unroll
        for (int w = 0; w < 8; w++) s += RS[tid * 8 + w];
        INV[tid] = 1.0f / s;
    }
    __syncthreads();
    const float invg  = INV[g];
    const float invg8 = INV[g + 8];

    // ================= loop2: GEMM2 (tf32), V frags direct LDG =================
    // stream steps: step = k2*2 + half, half 0 -> dt 0..3, half 1 -> dt 4..7
    float vacc[8][4];
    #pragma unroll
    for (int dt = 0; dt < 8; dt++)
        #pragma unroll
        for (int r = 0; r < 4; r++) vacc[dt][r] = 0.f;

    #pragma unroll
    for (int k2 = 0; k2 < 4; k2++) {
        const int s0 = k2 * 16;
        uint32_t ua[4], ub[4];
        ua[0] = rna(stg[g * 68 + s0 + t]);
        ua[1] = rna(stg[(g + 8) * 68 + s0 + t]);
        ua[2] = rna(stg[g * 68 + s0 + t + 4]);
        ua[3] = rna(stg[(g + 8) * 68 + s0 + t + 4]);
        ub[0] = rna(stg[g * 68 + s0 + 8 + t]);
        ub[1] = rna(stg[(g + 8) * 68 + s0 + 8 + t]);
        ub[2] = rna(stg[g * 68 + s0 + 8 + t + 4]);
        ub[3] = rna(stg[(g + 8) * 68 + s0 + 8 + t + 4]);

        #pragma unroll
        for (int hf = 0; hf < 2; hf++) {
            const int step = k2 * 2 + hf;
            if (step < 7) {
                const int stepn = step + 1;
                const int k2n = stepn >> 1, hfn = stepn & 1;
                #pragma unroll
                for (int j = 0; j < 4; j++)
                    Vb[stepn & 1][j] = vbase[(size_t)(hfn * 4 + j) * 1024 + k2n * 32];
            }
            const uint4* Bv = Vb[step & 1];
            #pragma unroll
            for (int j = 0; j < 4; j++) {
                const int dt = hf * 4 + j;
                mma_tf32(vacc[dt], ua, Bv[j].x, Bv[j].y);
                mma_tf32(vacc[dt], ub, Bv[j].z, Bv[j].w);
            }
        }
    }

    // ---- series write pass: coalesced 256B contiguous per row-slice ----
    {
        float* ser = out + V_SIZE + ((size_t)bh * 512 + l0) * 512 + cq * 64;
        #pragma unroll
        for (int r = 0; r < 16; r++) {
            float2 v = *(float2*)&stg[r * 68 + lane * 2];
            const float iv = INV[r];
            __stcs((float2*)(ser + (size_t)r * 512 + lane * 2),
                   make_float2(v.x * iv, v.y * iv));
        }
    }

    // ---- V cross-warp reduction via stash region (after series pass reads it) ----
    {
        float* part = stg;
        #pragma unroll
        for (int dt = 0; dt < 8; dt++) {
            *(float2*)(part + g * 64 + dt * 8 + 2 * t) =
                make_float2(vacc[dt][0] * invg, vacc[dt][1] * invg);
            *(float2*)(part + (g + 8) * 64 + dt * 8 + 2 * t) =
                make_float2(vacc[dt][2] * invg8, vacc[dt][3] * invg8);
        }
        __syncthreads();
        const int d = tid & 63;
        #pragma unroll
        for (int it = 0; it < 4; it++) {
            const int row = (tid >> 6) + it * 4;
            float s = 0.f;
            #pragma unroll
            for (int w = 0; w < 8; w++)
                s += ((float*)(sm + w * STASH_W))[row * 64 + d];
            __stcs(out + (((size_t)b * SEQ + l0 + row) * NHEAD + h) * HD + d, s);
        }
    }

    // ---- prior: warp sweeps 128-col chunks, lane*4 contiguous; warp-uniform skip ----
    {
        float amp_ = 0.f, ninv_ = 0.f;
        if (lane < 2) {
            int l = l0 + wid * 2 + lane;
            float x   = SG[((size_t)b * SEQ + l) * NHEAD + h];
            float smv = 1.0f / (1.0f + __expf(-5.0f * x));
            float yf  = smv + 1e-5f;
            float p3  = (float)exp((double)yf * 1.0986122886681098);
            float sig = p3 - 1.0f;
            amp_  = 0.3989422804014327f / sig;
            ninv_ = -1.0f / (2.0f * sig * sig);
        }
        float* priorBase = out + V_SIZE + SER_SIZE + ((size_t)bh * 512 + l0) * 512;
        #pragma unroll
        for (int rr = 0; rr < 2; rr++) {
            const float amp  = __shfl_sync(0xffffffffu, amp_, rr);
            const float ninv = __shfl_sync(0xffffffffu, ninv_, rr);
            const int l = l0 + wid * 2 + rr;
            float* pp = priorBase + (size_t)(wid * 2 + rr) * 512;
            #pragma unroll
            for (int j = 0; j < 4; j++) {
                const int c0 = j * 128;
                int dh = l - c0, dl = l - (c0 + 127);
                int admin = (dl <= 0 && dh >= 0) ? 0 : min(abs(dl), abs(dh));
                float* dst = pp + c0 + lane * 4;
                if (ninv * (float)(admin * admin) < -87.0f) {
                    __stcs((float4*)dst, make_float4(0.f, 0.f, 0.f, 0.f));
                } else {
                    const int s = c0 + lane * 4;
                    float d0 = (float)(l - s);
                    float d1 = (float)(l - (s + 1));
                    float d2 = (float)(l - (s + 2));
                    float d3 = (float)(l - (s + 3));
                    float4 o;
                    o.x = amp * __expf(ninv * d0 * d0);
                    o.y = amp * __expf(ninv * d1 * d1);
                    o.z = amp * __expf(ninv * d2 * d2);
                    o.w = amp * __expf(ninv * d3 * d3);
                    __stcs((float4*)dst, o);
                }
            }
        }
    }
}

extern "C" void kernel_launch(void* const* d_in, const int* in_sizes, int n_in,
                              void* d_out, int out_size) {
    (void)in_sizes; (void)n_in; (void)out_size;
    const float* q  = (const float*)d_in[0];
    const float* k  = (const float*)d_in[1];
    const float* v  = (const float*)d_in[2];
    const float* sg = (const float*)d_in[3];
    float* out = (float*)d_out;

    cudaFuncSetAttribute(anomaly_mma, cudaFuncAttributeMaxDynamicSharedMemorySize,
                         (int)SMEM_BYTES);

    prepack<<<PREN / 256, 256>>>(q, k, v);
    anomaly_mma<<<NBATCH * NHEAD * 32, 256, SMEM_BYTES>>>(sg, out);
}

// round 13
// speedup vs baseline: 1.2908x; 1.2908x over previous
#include <cuda_runtime.h>
#include <cuda_fp16.h>
#include <math.h>
#include <stdint.h>

#define NBATCH 32
#define NHEAD  8
#define SEQ    512
#define HD     64

constexpr size_t V_SIZE   = (size_t)NBATCH * SEQ * NHEAD * HD;     // 8388608
constexpr size_t SER_SIZE = (size_t)NBATCH * NHEAD * SEQ * SEQ;    // 67108864

// ---- prepacked fp16 fragment arrays (fragment-major, rne-rounded) ----
// KB: uint4 idx = ((bh*64 + st)*2 + c)*32 + lane   {kt=2c:b0,b1, kt=2c+1:b0,b1}
// VB: uint4 idx = (((bh*8 + cq)*4 + k2)*4 + j)*32 + lane {dt=2j:b0,b1, dt=2j+1:b0,b1}
// QA: uint4 idx = ((bh*32 + rt)*4 + kt)*32 + lane  {a0,a1,a2,a3}
__device__ uint4 d_KB[(size_t)256 * 64 * 2 * 32];
__device__ uint4 d_VB[(size_t)256 * 8 * 4 * 4 * 32];
__device__ uint4 d_QA[(size_t)256 * 32 * 4 * 32];

constexpr int KB4N = 256 * 64 * 2 * 32;     // 1048576
constexpr int VB4N = 256 * 8 * 4 * 4 * 32;  // 1048576
constexpr int QA4N = 256 * 32 * 4 * 32;     // 1048576
constexpr int PRE4N = KB4N + VB4N + QA4N;   // 3145728

// ---- smem layout (bytes) ----
// A: per-warp 4KB double buffer (2 x 2KB k2-granule), K in loop1 / V in loop2
// B: per-warp 4352B fp32 P stash [16][68]; reused as V-partials
constexpr uint32_t A_OFF   = 0;        // 8 * 4096 = 32768
constexpr uint32_t B_OFF   = 32768;    // 8 * 4352 = 34816
constexpr uint32_t STASH_W = 4352;
constexpr uint32_t RS_OFF  = 67584;
constexpr uint32_t INV_OFF = 68096;
constexpr uint32_t SMEM_BYTES = 68160;

__device__ __forceinline__ uint32_t s2u(const void* p) {
    uint32_t a;
    asm("{ .reg .u64 t; cvta.to.shared.u64 t, %1; cvt.u32.u64 %0, t; }" : "=r"(a) : "l"(p));
    return a;
}
__device__ __forceinline__ void cp16(uint32_t dst, const void* src) {
    asm volatile("cp.async.cg.shared.global [%0], [%1], 16;" :: "r"(dst), "l"(src) : "memory");
}
__device__ __forceinline__ void cpcommit() { asm volatile("cp.async.commit_group;" ::: "memory"); }
__device__ __forceinline__ void cpwait0()  { asm volatile("cp.async.wait_group 0;" ::: "memory"); }
__device__ __forceinline__ void cpwait1()  { asm volatile("cp.async.wait_group 1;" ::: "memory"); }

__device__ __forceinline__ uint32_t h2(float x, float y) {
    __half2 v = __floats2half2_rn(x, y);
    return *(uint32_t*)&v;
}

__device__ __forceinline__ void mma_f16(float* c, const uint32_t* a, uint32_t b0, uint32_t b1) {
    asm volatile(
        "mma.sync.aligned.m16n8k16.row.col.f32.f16.f16.f32 "
        "{%0,%1,%2,%3},{%4,%5,%6,%7},{%8,%9},{%0,%1,%2,%3};\n"
        : "+f"(c[0]), "+f"(c[1]), "+f"(c[2]), "+f"(c[3])
        : "r"(a[0]), "r"(a[1]), "r"(a[2]), "r"(a[3]), "r"(b0), "r"(b1));
}

// ---------------- prepack: Q, K, V -> fp16 fragment-major ----------------
__global__ void __launch_bounds__(256) prepack(const float* __restrict__ Q,
                                               const float* __restrict__ K,
                                               const float* __restrict__ V) {
    int idx = blockIdx.x * 256 + threadIdx.x;
    int lane = idx & 31, g = (lane >> 2), t = lane & 3;
    if (idx < KB4N) {
        int c = (idx >> 5) & 1, st = (idx >> 6) & 63, bh = idx >> 12;
        int b = bh >> 3, h = bh & 7;
        int s = st * 8 + g;
        const float* kp = K + (((size_t)b * SEQ + s) * NHEAD + h) * HD;
        int ka = (2 * c) * 16 + 2 * t;
        int kb = (2 * c + 1) * 16 + 2 * t;
        d_KB[idx] = make_uint4(h2(kp[ka], kp[ka + 1]), h2(kp[ka + 8], kp[ka + 9]),
                               h2(kp[kb], kp[kb + 1]), h2(kp[kb + 8], kp[kb + 9]));
    } else if (idx < KB4N + VB4N) {
        int i = idx - KB4N;
        int j = (i >> 5) & 3, k2 = (i >> 7) & 3, cq = (i >> 9) & 7, bh = i >> 12;
        int b = bh >> 3, h = bh & 7;
        int s0 = cq * 64 + k2 * 16;
        int d0 = (2 * j) * 8 + g, d1 = (2 * j + 1) * 8 + g;
        const float* vp = V + ((size_t)b * SEQ * NHEAD + h) * HD;
        d_VB[i] = make_uint4(
            h2(vp[(size_t)(s0 + 2 * t) * 512 + d0],     vp[(size_t)(s0 + 2 * t + 1) * 512 + d0]),
            h2(vp[(size_t)(s0 + 2 * t + 8) * 512 + d0], vp[(size_t)(s0 + 2 * t + 9) * 512 + d0]),
            h2(vp[(size_t)(s0 + 2 * t) * 512 + d1],     vp[(size_t)(s0 + 2 * t + 1) * 512 + d1]),
            h2(vp[(size_t)(s0 + 2 * t + 8) * 512 + d1], vp[(size_t)(s0 + 2 * t + 9) * 512 + d1]));
    } else if (idx < PRE4N) {
        int i = idx - KB4N - VB4N;
        int kt = (i >> 5) & 3, rt = (i >> 7) & 31, bh = i >> 12;
        int b = bh >> 3, h = bh & 7;
        int k0 = kt * 16 + 2 * t;
        const float* qp = Q + (((size_t)b * SEQ + rt * 16) * NHEAD + h) * HD;
        d_QA[i] = make_uint4(
            h2(qp[(size_t)g * 512 + k0],           qp[(size_t)g * 512 + k0 + 1]),
            h2(qp[(size_t)(g + 8) * 512 + k0],     qp[(size_t)(g + 8) * 512 + k0 + 1]),
            h2(qp[(size_t)g * 512 + k0 + 8],       qp[(size_t)g * 512 + k0 + 9]),
            h2(qp[(size_t)(g + 8) * 512 + k0 + 8], qp[(size_t)(g + 8) * 512 + k0 + 9]));
    }
}

// ---------------- main ----------------
// CTA: 16 rows x 512 cols. 8 warps = 8 col-slices of 64.
__global__ void __launch_bounds__(256, 2) anomaly_mma(const float* __restrict__ SG,
                                                      float* __restrict__ out) {
    extern __shared__ char sm[];
    const uint32_t smb = s2u(sm);
    float* RS  = (float*)(sm + RS_OFF);
    float* INV = (float*)(sm + INV_OFF);

    const int tid = threadIdx.x, lane = tid & 31, wid = tid >> 5;
    const int g = lane >> 2, t = lane & 3;
    const int mt = blockIdx.x & 31;
    const int bh = blockIdx.x >> 5;
    const int h = bh & 7, b = bh >> 3;
    const int l0 = mt * 16;
    const int cq = wid;

    const uint32_t Aw = smb + A_OFF + wid * 4096;
    char* Awc = sm + A_OFF + wid * 4096;
    float* stg = (float*)(sm + B_OFF + wid * STASH_W);

    const char* srcK = (const char*)d_KB + (size_t)(bh * 64 + cq * 8) * 1024;
    const char* srcV = (const char*)d_VB + (size_t)(bh * 8 + cq) * 8192;

    // prologue: K k2=0 (stiles 0,1) into buffer 0
    #pragma unroll
    for (int n = 0; n < 2; n++)
        #pragma unroll
        for (int c = 0; c < 2; c++)
            cp16(Aw + n * 1024 + c * 512 + lane * 16,
                 srcK + (size_t)n * 1024 + c * 512 + lane * 16);
    cpcommit();

    // ---- Q fragments (fp16) ----
    uint32_t qa[4][4];
    {
        const uint4* qp4 = d_QA + ((size_t)(bh * 32 + mt) * 4) * 32 + lane;
        #pragma unroll
        for (int kt = 0; kt < 4; kt++) {
            uint4 v = qp4[kt * 32];
            qa[kt][0] = v.x; qa[kt][1] = v.y; qa[kt][2] = v.z; qa[kt][3] = v.w;
        }
    }

    // ================= loop1: GEMM1 (fp16) -> exp -> fp32 stash =================
    float rs0 = 0.f, rs1 = 0.f;
    #pragma unroll
    for (int k2 = 0; k2 < 4; k2++) {
        if (k2 < 3) {
            const int nb = (k2 + 1) & 1;
            #pragma unroll
            for (int n = 0; n < 2; n++)
                #pragma unroll
                for (int c = 0; c < 2; c++)
                    cp16(Aw + nb * 2048 + n * 1024 + c * 512 + lane * 16,
                         srcK + (size_t)(2 * (k2 + 1) + n) * 1024 + c * 512 + lane * 16);
            cpcommit();
            cpwait1();
        } else {
            cpwait0();
        }

        const char* kb = Awc + (k2 & 1) * 2048;
        float aA[2][4], aB[2][4];
        #pragma unroll
        for (int n = 0; n < 2; n++)
            #pragma unroll
            for (int r = 0; r < 4; r++) { aA[n][r] = 0.f; aB[n][r] = 0.f; }

        #pragma unroll
        for (int n = 0; n < 2; n++) {
            uint4 X = *(const uint4*)(kb + n * 1024 + lane * 16);        // kt0, kt1
            uint4 Y = *(const uint4*)(kb + n * 1024 + 512 + lane * 16);  // kt2, kt3
            mma_f16(aA[n], qa[0], X.x, X.y);
            mma_f16(aB[n], qa[1], X.z, X.w);
            mma_f16(aA[n], qa[2], Y.x, Y.y);
            mma_f16(aB[n], qa[3], Y.z, Y.w);
        }

        float p[2][4];
        #pragma unroll
        for (int n = 0; n < 2; n++)
            #pragma unroll
            for (int r = 0; r < 4; r++)
                p[n][r] = __expf(0.125f * (aA[n][r] + aB[n][r]));

        rs0 += p[0][0] + p[0][1] + p[1][0] + p[1][1];
        rs1 += p[0][2] + p[0][3] + p[1][2] + p[1][3];

        #pragma unroll
        for (int n = 0; n < 2; n++) {
            const int col = k2 * 16 + n * 8 + 2 * t;
            *(float2*)&stg[g * 68 + col]       = make_float2(p[n][0], p[n][1]);
            *(float2*)&stg[(g + 8) * 68 + col] = make_float2(p[n][2], p[n][3]);
        }
    }

    // ---- V prologue prefetch k2=0 (overlaps rowsum barrier phase) ----
    #pragma unroll
    for (int j = 0; j < 4; j++)
        cp16(Aw + j * 512 + lane * 16, srcV + (size_t)j * 512 + lane * 16);
    cpcommit();

    // ---- rowsums -> inv ----
    rs0 += __shfl_xor_sync(0xffffffffu, rs0, 1);
    rs0 += __shfl_xor_sync(0xffffffffu, rs0, 2);
    rs1 += __shfl_xor_sync(0xffffffffu, rs1, 1);
    rs1 += __shfl_xor_sync(0xffffffffu, rs1, 2);
    if (t == 0) {
        RS[g * 8 + wid]       = rs0;
        RS[(g + 8) * 8 + wid] = rs1;
    }
    __syncthreads();
    if (tid < 16) {
        float s = 0.f;
        #pragma unroll
        for (int w = 0; w < 8; w++) s += RS[tid * 8 + w];
        INV[tid] = 1.0f / s;
    }
    __syncthreads();
    const float invg  = INV[g];
    const float invg8 = INV[g + 8];

    // ================= loop2: GEMM2 (fp16) =================
    float vacc[8][4];
    #pragma unroll
    for (int dt = 0; dt < 8; dt++)
        #pragma unroll
        for (int r = 0; r < 4; r++) vacc[dt][r] = 0.f;

    #pragma unroll
    for (int k2 = 0; k2 < 4; k2++) {
        if (k2 < 3) {
            const int nb = (k2 + 1) & 1;
            #pragma unroll
            for (int j = 0; j < 4; j++)
                cp16(Aw + nb * 2048 + j * 512 + lane * 16,
                     srcV + (size_t)(k2 + 1) * 2048 + j * 512 + lane * 16);
            cpcommit();
            cpwait1();
        } else {
            cpwait0();
        }

        // A frag from stash (float2 pairs -> half2); k = s0+2t .. with +8 partner
        const int s0 = k2 * 16;
        uint32_t ua[4];
        {
            float2 p0 = *(float2*)&stg[g * 68 + s0 + 2 * t];
            float2 p1 = *(float2*)&stg[(g + 8) * 68 + s0 + 2 * t];
            float2 p2 = *(float2*)&stg[g * 68 + s0 + 2 * t + 8];
            float2 p3 = *(float2*)&stg[(g + 8) * 68 + s0 + 2 * t + 8];
            ua[0] = h2(p0.x, p0.y);
            ua[1] = h2(p1.x, p1.y);
            ua[2] = h2(p2.x, p2.y);
            ua[3] = h2(p3.x, p3.y);
        }

        const char* vb = Awc + (k2 & 1) * 2048;
        #pragma unroll
        for (int j = 0; j < 4; j++) {
            uint4 Bv = *(const uint4*)(vb + j * 512 + lane * 16);
            mma_f16(vacc[2 * j],     ua, Bv.x, Bv.y);
            mma_f16(vacc[2 * j + 1], ua, Bv.z, Bv.w);
        }
    }

    // ---- series write pass: coalesced 256B contiguous per row-slice ----
    {
        float* ser = out + V_SIZE + ((size_t)bh * 512 + l0) * 512 + cq * 64;
        #pragma unroll
        for (int r = 0; r < 16; r++) {
            float2 v = *(float2*)&stg[r * 68 + lane * 2];
            const float iv = INV[r];
            __stcs((float2*)(ser + (size_t)r * 512 + lane * 2),
                   make_float2(v.x * iv, v.y * iv));
        }
    }

    // ---- V cross-warp reduction via stash region ----
    {
        float* part = stg;
        #pragma unroll
        for (int dt = 0; dt < 8; dt++) {
            *(float2*)(part + g * 64 + dt * 8 + 2 * t) =
                make_float2(vacc[dt][0] * invg, vacc[dt][1] * invg);
            *(float2*)(part + (g + 8) * 64 + dt * 8 + 2 * t) =
                make_float2(vacc[dt][2] * invg8, vacc[dt][3] * invg8);
        }
        __syncthreads();
        const int d = tid & 63;
        #pragma unroll
        for (int it = 0; it < 4; it++) {
            const int row = (tid >> 6) + it * 4;
            float s = 0.f;
            #pragma unroll
            for (int w = 0; w < 8; w++)
                s += ((float*)(sm + B_OFF + w * STASH_W))[row * 64 + d];
            __stcs(out + (((size_t)b * SEQ + l0 + row) * NHEAD + h) * HD + d, s);
        }
    }

    // ---- prior: warp sweeps 128-col chunks, lane*4 contiguous; warp-uniform skip ----
    {
        float amp_ = 0.f, ninv_ = 0.f;
        if (lane < 2) {
            int l = l0 + wid * 2 + lane;
            float x   = SG[((size_t)b * SEQ + l) * NHEAD + h];
            float smv = 1.0f / (1.0f + __expf(-5.0f * x));
            float yf  = smv + 1e-5f;
            float p3  = (float)exp((double)yf * 1.0986122886681098);
            float sig = p3 - 1.0f;
            amp_  = 0.3989422804014327f / sig;
            ninv_ = -1.0f / (2.0f * sig * sig);
        }
        float* priorBase = out + V_SIZE + SER_SIZE + ((size_t)bh * 512 + l0) * 512;
        #pragma unroll
        for (int rr = 0; rr < 2; rr++) {
            const float amp  = __shfl_sync(0xffffffffu, amp_, rr);
            const float ninv = __shfl_sync(0xffffffffu, ninv_, rr);
            const int l = l0 + wid * 2 + rr;
            float* pp = priorBase + (size_t)(wid * 2 + rr) * 512;
            #pragma unroll
            for (int j = 0; j < 4; j++) {
                const int c0 = j * 128;
                int dh = l - c0, dl = l - (c0 + 127);
                int admin = (dl <= 0 && dh >= 0) ? 0 : min(abs(dl), abs(dh));
                float* dst = pp + c0 + lane * 4;
                if (ninv * (float)(admin * admin) < -87.0f) {
                    __stcs((float4*)dst, make_float4(0.f, 0.f, 0.f, 0.f));
                } else {
                    const int s = c0 + lane * 4;
                    float d0 = (float)(l - s);
                    float d1 = (float)(l - (s + 1));
                    float d2 = (float)(l - (s + 2));
                    float d3 = (float)(l - (s + 3));
                    float4 o;
                    o.x = amp * __expf(ninv * d0 * d0);
                    o.y = amp * __expf(ninv * d1 * d1);
                    o.z = amp * __expf(ninv * d2 * d2);
                    o.w = amp * __expf(ninv * d3 * d3);
                    __stcs((float4*)dst, o);
                }
            }
        }
    }
}

extern "C" void kernel_launch(void* const* d_in, const int* in_sizes, int n_in,
                              void* d_out, int out_size) {
    (void)in_sizes; (void)n_in; (void)out_size;
    const float* q  = (const float*)d_in[0];
    const float* k  = (const float*)d_in[1];
    const float* v  = (const float*)d_in[2];
    const float* sg = (const float*)d_in[3];
    float* out = (float*)d_out;

    cudaFuncSetAttribute(anomaly_mma, cudaFuncAttributeMaxDynamicSharedMemorySize,
                         (int)SMEM_BYTES);

    prepack<<<PRE4N / 256, 256>>>(q, k, v);
    anomaly_mma<<<NBATCH * NHEAD * 32, 256, SMEM_BYTES>>>(sg, out);
}

// round 14
// speedup vs baseline: 1.4636x; 1.1338x over previous
#include <cuda_runtime.h>
#include <cuda_fp16.h>
#include <math.h>
#include <stdint.h>

#define NBATCH 32
#define NHEAD  8
#define SEQ    512
#define HD     64

constexpr size_t V_SIZE   = (size_t)NBATCH * SEQ * NHEAD * HD;     // 8388608
constexpr size_t SER_SIZE = (size_t)NBATCH * NHEAD * SEQ * SEQ;    // 67108864

// ---- prepacked fp16 fragment arrays (fragment-major, rne-rounded) ----
// KB: uint4 idx = ((bh*64 + st)*2 + c)*32 + lane   {kt=2c:b0,b1, kt=2c+1:b0,b1}
// VB: uint4 idx = (((bh*8 + cq)*4 + k2)*4 + j)*32 + lane {dt=2j:b0,b1, dt=2j+1:b0,b1}
// QA: uint4 idx = ((bh*32 + rt)*4 + kt)*32 + lane  {a0,a1,a2,a3}
__device__ uint4 d_KB[(size_t)256 * 64 * 2 * 32];
__device__ uint4 d_VB[(size_t)256 * 8 * 4 * 4 * 32];
__device__ uint4 d_QA[(size_t)256 * 32 * 4 * 32];

constexpr int KB4N = 256 * 64 * 2 * 32;
constexpr int VB4N = 256 * 8 * 4 * 4 * 32;
constexpr int QA4N = 256 * 32 * 4 * 32;
constexpr int PRE4N = KB4N + VB4N + QA4N;

// ---- smem layout (bytes) ----
constexpr uint32_t A_OFF   = 0;        // 8 * 4096 = 32768 (per-warp double buffer)
constexpr uint32_t B_OFF   = 32768;    // 8 * 4352 = 34816 (per-warp fp32 P stash [16][68])
constexpr uint32_t STASH_W = 4352;
constexpr uint32_t RS_OFF  = 67584;
constexpr uint32_t INV_OFF = 68096;
constexpr uint32_t SMEM_BYTES = 68160;

__device__ __forceinline__ uint32_t s2u(const void* p) {
    uint32_t a;
    asm("{ .reg .u64 t; cvta.to.shared.u64 t, %1; cvt.u32.u64 %0, t; }" : "=r"(a) : "l"(p));
    return a;
}
__device__ __forceinline__ void cp16(uint32_t dst, const void* src) {
    asm volatile("cp.async.cg.shared.global [%0], [%1], 16;" :: "r"(dst), "l"(src) : "memory");
}
__device__ __forceinline__ void cpcommit() { asm volatile("cp.async.commit_group;" ::: "memory"); }
__device__ __forceinline__ void cpwait0()  { asm volatile("cp.async.wait_group 0;" ::: "memory"); }
__device__ __forceinline__ void cpwait1()  { asm volatile("cp.async.wait_group 1;" ::: "memory"); }

__device__ __forceinline__ uint32_t h2(float x, float y) {
    __half2 v = __floats2half2_rn(x, y);
    return *(uint32_t*)&v;
}

__device__ __forceinline__ void mma_f16(float* c, const uint32_t* a, uint32_t b0, uint32_t b1) {
    asm volatile(
        "mma.sync.aligned.m16n8k16.row.col.f32.f16.f16.f32 "
        "{%0,%1,%2,%3},{%4,%5,%6,%7},{%8,%9},{%0,%1,%2,%3};\n"
        : "+f"(c[0]), "+f"(c[1]), "+f"(c[2]), "+f"(c[3])
        : "r"(a[0]), "r"(a[1]), "r"(a[2]), "r"(a[3]), "r"(b0), "r"(b1));
}

// ---------------- prepack (unchanged from round 13) ----------------
__global__ void __launch_bounds__(256) prepack(const float* __restrict__ Q,
                                               const float* __restrict__ K,
                                               const float* __restrict__ V) {
    int idx = blockIdx.x * 256 + threadIdx.x;
    int lane = idx & 31, g = (lane >> 2), t = lane & 3;
    if (idx < KB4N) {
        int c = (idx >> 5) & 1, st = (idx >> 6) & 63, bh = idx >> 12;
        int b = bh >> 3, h = bh & 7;
        int s = st * 8 + g;
        const float* kp = K + (((size_t)b * SEQ + s) * NHEAD + h) * HD;
        int ka = (2 * c) * 16 + 2 * t;
        int kb = (2 * c + 1) * 16 + 2 * t;
        d_KB[idx] = make_uint4(h2(kp[ka], kp[ka + 1]), h2(kp[ka + 8], kp[ka + 9]),
                               h2(kp[kb], kp[kb + 1]), h2(kp[kb + 8], kp[kb + 9]));
    } else if (idx < KB4N + VB4N) {
        int i = idx - KB4N;
        int j = (i >> 5) & 3, k2 = (i >> 7) & 3, cq = (i >> 9) & 7, bh = i >> 12;
        int b = bh >> 3, h = bh & 7;
        int s0 = cq * 64 + k2 * 16;
        int d0 = (2 * j) * 8 + g, d1 = (2 * j + 1) * 8 + g;
        const float* vp = V + ((size_t)b * SEQ * NHEAD + h) * HD;
        d_VB[i] = make_uint4(
            h2(vp[(size_t)(s0 + 2 * t) * 512 + d0],     vp[(size_t)(s0 + 2 * t + 1) * 512 + d0]),
            h2(vp[(size_t)(s0 + 2 * t + 8) * 512 + d0], vp[(size_t)(s0 + 2 * t + 9) * 512 + d0]),
            h2(vp[(size_t)(s0 + 2 * t) * 512 + d1],     vp[(size_t)(s0 + 2 * t + 1) * 512 + d1]),
            h2(vp[(size_t)(s0 + 2 * t + 8) * 512 + d1], vp[(size_t)(s0 + 2 * t + 9) * 512 + d1]));
    } else if (idx < PRE4N) {
        int i = idx - KB4N - VB4N;
        int kt = (i >> 5) & 3, rt = (i >> 7) & 31, bh = i >> 12;
        int b = bh >> 3, h = bh & 7;
        int k0 = kt * 16 + 2 * t;
        const float* qp = Q + (((size_t)b * SEQ + rt * 16) * NHEAD + h) * HD;
        d_QA[i] = make_uint4(
            h2(qp[(size_t)g * 512 + k0],           qp[(size_t)g * 512 + k0 + 1]),
            h2(qp[(size_t)(g + 8) * 512 + k0],     qp[(size_t)(g + 8) * 512 + k0 + 1]),
            h2(qp[(size_t)g * 512 + k0 + 8],       qp[(size_t)g * 512 + k0 + 9]),
            h2(qp[(size_t)(g + 8) * 512 + k0 + 8], qp[(size_t)(g + 8) * 512 + k0 + 9]));
    }
}

// ---------------- main ----------------
// CTA: 16 rows x 512 cols. loop1: 8 warps = 8 col-slices of 64.
// loop2: warp = (sh = s-range 128, dh = d-half 32), vacc 16 regs -> 3 CTAs/SM.
__global__ void __launch_bounds__(256, 3) anomaly_mma(const float* __restrict__ SG,
                                                      float* __restrict__ out) {
    extern __shared__ char sm[];
    const uint32_t smb = s2u(sm);
    float* RS  = (float*)(sm + RS_OFF);
    float* INV = (float*)(sm + INV_OFF);

    const int tid = threadIdx.x, lane = tid & 31, wid = tid >> 5;
    const int g = lane >> 2, t = lane & 3;
    const int mt = blockIdx.x & 31;
    const int bh = blockIdx.x >> 5;
    const int h = bh & 7, b = bh >> 3;
    const int l0 = mt * 16;
    const int cq = wid;

    const uint32_t Aw = smb + A_OFF + wid * 4096;
    char* Awc = sm + A_OFF + wid * 4096;
    float* stg = (float*)(sm + B_OFF + wid * STASH_W);

    const char* srcK = (const char*)d_KB + (size_t)(bh * 64 + cq * 8) * 1024;

    // prologue: K k2=0 (stiles 0,1) into buffer 0
    #pragma unroll
    for (int n = 0; n < 2; n++)
        #pragma unroll
        for (int c = 0; c < 2; c++)
            cp16(Aw + n * 1024 + c * 512 + lane * 16,
                 srcK + (size_t)n * 1024 + c * 512 + lane * 16);
    cpcommit();

    // ---- Q fragments (fp16) ----
    uint32_t qa[4][4];
    {
        const uint4* qp4 = d_QA + ((size_t)(bh * 32 + mt) * 4) * 32 + lane;
        #pragma unroll
        for (int kt = 0; kt < 4; kt++) {
            uint4 v = qp4[kt * 32];
            qa[kt][0] = v.x; qa[kt][1] = v.y; qa[kt][2] = v.z; qa[kt][3] = v.w;
        }
    }

    // ================= loop1: GEMM1 (fp16) -> exp -> fp32 stash =================
    float rs0 = 0.f, rs1 = 0.f;
    #pragma unroll
    for (int k2 = 0; k2 < 4; k2++) {
        if (k2 < 3) {
            const int nb = (k2 + 1) & 1;
            #pragma unroll
            for (int n = 0; n < 2; n++)
                #pragma unroll
                for (int c = 0; c < 2; c++)
                    cp16(Aw + nb * 2048 + n * 1024 + c * 512 + lane * 16,
                         srcK + (size_t)(2 * (k2 + 1) + n) * 1024 + c * 512 + lane * 16);
            cpcommit();
            cpwait1();
        } else {
            cpwait0();
        }

        const char* kb = Awc + (k2 & 1) * 2048;
        float aA[2][4], aB[2][4];
        #pragma unroll
        for (int n = 0; n < 2; n++)
            #pragma unroll
            for (int r = 0; r < 4; r++) { aA[n][r] = 0.f; aB[n][r] = 0.f; }

        #pragma unroll
        for (int n = 0; n < 2; n++) {
            uint4 X = *(const uint4*)(kb + n * 1024 + lane * 16);
            uint4 Y = *(const uint4*)(kb + n * 1024 + 512 + lane * 16);
            mma_f16(aA[n], qa[0], X.x, X.y);
            mma_f16(aB[n], qa[1], X.z, X.w);
            mma_f16(aA[n], qa[2], Y.x, Y.y);
            mma_f16(aB[n], qa[3], Y.z, Y.w);
        }

        float p[2][4];
        #pragma unroll
        for (int n = 0; n < 2; n++)
            #pragma unroll
            for (int r = 0; r < 4; r++)
                p[n][r] = __expf(0.125f * (aA[n][r] + aB[n][r]));

        rs0 += p[0][0] + p[0][1] + p[1][0] + p[1][1];
        rs1 += p[0][2] + p[0][3] + p[1][2] + p[1][3];

        #pragma unroll
        for (int n = 0; n < 2; n++) {
            const int col = k2 * 16 + n * 8 + 2 * t;
            *(float2*)&stg[g * 68 + col]       = make_float2(p[n][0], p[n][1]);
            *(float2*)&stg[(g + 8) * 68 + col] = make_float2(p[n][2], p[n][3]);
        }
    }

    // ---- loop2 warp roles + V prologue prefetch (overlaps rowsum barrier) ----
    const int sh = wid >> 1;     // s-range [sh*128, +128)
    const int dh = wid & 1;      // d-half  [dh*32, +32)
    // V source for step st (0..7): cq' = 2sh + (st>>2), k2 = st&3, j base = 2dh
    const char* srcV0 = (const char*)d_VB +
        ((((size_t)(bh * 8 + 2 * sh) * 4 + 0) * 4 + 2 * dh) * 32) * 16;
    cp16(Aw + lane * 16,       srcV0 + lane * 16);
    cp16(Aw + 512 + lane * 16, srcV0 + 512 + lane * 16);
    cpcommit();

    // ---- rowsums -> inv ----
    rs0 += __shfl_xor_sync(0xffffffffu, rs0, 1);
    rs0 += __shfl_xor_sync(0xffffffffu, rs0, 2);
    rs1 += __shfl_xor_sync(0xffffffffu, rs1, 1);
    rs1 += __shfl_xor_sync(0xffffffffu, rs1, 2);
    if (t == 0) {
        RS[g * 8 + wid]       = rs0;
        RS[(g + 8) * 8 + wid] = rs1;
    }
    __syncthreads();   // also publishes all stash writes for cross-warp loop2 reads
    if (tid < 16) {
        float s = 0.f;
        #pragma unroll
        for (int w = 0; w < 8; w++) s += RS[tid * 8 + w];
        INV[tid] = 1.0f / s;
    }
    __syncthreads();
    const float invg  = INV[g];
    const float invg8 = INV[g + 8];

    // ================= loop2: GEMM2 (fp16), d-split, vacc = 16 regs =================
    float vacc[4][4];
    #pragma unroll
    for (int j = 0; j < 4; j++)
        #pragma unroll
        for (int r = 0; r < 4; r++) vacc[j][r] = 0.f;

    #pragma unroll
    for (int st = 0; st < 8; st++) {
        if (st < 7) {
            const int stn = st + 1;
            const char* srcn = (const char*)d_VB +
                ((((size_t)(bh * 8 + 2 * sh + (stn >> 2)) * 4 + (stn & 3)) * 4 + 2 * dh) * 32) * 16;
            const uint32_t dstb = Aw + (stn & 1) * 1024;
            cp16(dstb + lane * 16,       srcn + lane * 16);
            cp16(dstb + 512 + lane * 16, srcn + 512 + lane * 16);
            cpcommit();
            cpwait1();
        } else {
            cpwait0();
        }

        // A frag from the stash of warp (2sh + (st>>2)), col (st&3)*16
        const float* stq = (const float*)(sm + B_OFF + (2 * sh + (st >> 2)) * STASH_W);
        const int s0 = (st & 3) * 16;
        uint32_t ua[4];
        {
            float2 p0 = *(const float2*)&stq[g * 68 + s0 + 2 * t];
            float2 p1 = *(const float2*)&stq[(g + 8) * 68 + s0 + 2 * t];
            float2 p2 = *(const float2*)&stq[g * 68 + s0 + 2 * t + 8];
            float2 p3 = *(const float2*)&stq[(g + 8) * 68 + s0 + 2 * t + 8];
            ua[0] = h2(p0.x, p0.y);
            ua[1] = h2(p1.x, p1.y);
            ua[2] = h2(p2.x, p2.y);
            ua[3] = h2(p3.x, p3.y);
        }

        const char* vb = Awc + (st & 1) * 1024;
        uint4 B0 = *(const uint4*)(vb + lane * 16);        // dt_local 0,1
        uint4 B1 = *(const uint4*)(vb + 512 + lane * 16);  // dt_local 2,3
        mma_f16(vacc[0], ua, B0.x, B0.y);
        mma_f16(vacc[1], ua, B0.z, B0.w);
        mma_f16(vacc[2], ua, B1.x, B1.y);
        mma_f16(vacc[3], ua, B1.z, B1.w);
    }

    // ---- series write pass: coalesced, each warp its own col-slice (own stash) ----
    {
        float* ser = out + V_SIZE + ((size_t)bh * 512 + l0) * 512 + cq * 64;
        #pragma unroll
        for (int r = 0; r < 16; r++) {
            float2 v = *(float2*)&stg[r * 68 + lane * 2];
            const float iv = INV[r];
            __stcs((float2*)(ser + (size_t)r * 512 + lane * 2),
                   make_float2(v.x * iv, v.y * iv));
        }
    }

    // ---- V cross-warp reduction (4 partials per (row,d)) ----
    __syncthreads();   // all warps done reading stashes (loop2 cross-warp + series)
    {
        float* part = stg;   // [16 rows][32 d-local] = 2KB
        #pragma unroll
        for (int j = 0; j < 4; j++) {
            part[g * 32 + j * 8 + 2 * t]           = vacc[j][0] * invg;
            part[g * 32 + j * 8 + 2 * t + 1]       = vacc[j][1] * invg;
            part[(g + 8) * 32 + j * 8 + 2 * t]     = vacc[j][2] * invg8;
            part[(g + 8) * 32 + j * 8 + 2 * t + 1] = vacc[j][3] * invg8;
        }
        __syncthreads();
        const int d = tid & 63;
        const int dv = d & 31, wsel = d >> 5;
        #pragma unroll
        for (int it = 0; it < 4; it++) {
            const int row = (tid >> 6) + it * 4;
            float s = 0.f;
            #pragma unroll
            for (int shh = 0; shh < 4; shh++)
                s += ((float*)(sm + B_OFF + (shh * 2 + wsel) * STASH_W))[row * 32 + dv];
            __stcs(out + (((size_t)b * SEQ + l0 + row) * NHEAD + h) * HD + d, s);
        }
    }

    // ---- prior: warp sweeps 128-col chunks, lane*4 contiguous; warp-uniform skip ----
    {
        float amp_ = 0.f, ninv_ = 0.f;
        if (lane < 2) {
            int l = l0 + wid * 2 + lane;
            float x   = SG[((size_t)b * SEQ + l) * NHEAD + h];
            float smv = 1.0f / (1.0f + __expf(-5.0f * x));
            float yf  = smv + 1e-5f;
            float p3  = (float)exp((double)yf * 1.0986122886681098);
            float sig = p3 - 1.0f;
            amp_  = 0.3989422804014327f / sig;
            ninv_ = -1.0f / (2.0f * sig * sig);
        }
        float* priorBase = out + V_SIZE + SER_SIZE + ((size_t)bh * 512 + l0) * 512;
        #pragma unroll
        for (int rr = 0; rr < 2; rr++) {
            const float amp  = __shfl_sync(0xffffffffu, amp_, rr);
            const float ninv = __shfl_sync(0xffffffffu, ninv_, rr);
            const int l = l0 + wid * 2 + rr;
            float* pp = priorBase + (size_t)(wid * 2 + rr) * 512;
            #pragma unroll
            for (int j = 0; j < 4; j++) {
                const int c0 = j * 128;
                int dhh = l - c0, dll = l - (c0 + 127);
                int admin = (dll <= 0 && dhh >= 0) ? 0 : min(abs(dll), abs(dhh));
                float* dst = pp + c0 + lane * 4;
                if (ninv * (float)(admin * admin) < -87.0f) {
                    __stcs((float4*)dst, make_float4(0.f, 0.f, 0.f, 0.f));
                } else {
                    const int s = c0 + lane * 4;
                    float d0 = (float)(l - s);
                    float d1 = (float)(l - (s + 1));
                    float d2 = (float)(l - (s + 2));
                    float d3 = (float)(l - (s + 3));
                    float4 o;
                    o.x = amp * __expf(ninv * d0 * d0);
                    o.y = amp * __expf(ninv * d1 * d1);
                    o.z = amp * __expf(ninv * d2 * d2);
                    o.w = amp * __expf(ninv * d3 * d3);
                    __stcs((float4*)dst, o);
                }
            }
        }
    }
}

extern "C" void kernel_launch(void* const* d_in, const int* in_sizes, int n_in,
                              void* d_out, int out_size) {
    (void)in_sizes; (void)n_in; (void)out_size;
    const float* q  = (const float*)d_in[0];
    const float* k  = (const float*)d_in[1];
    const float* v  = (const float*)d_in[2];
    const float* sg = (const float*)d_in[3];
    float* out = (float*)d_out;

    cudaFuncSetAttribute(anomaly_mma, cudaFuncAttributeMaxDynamicSharedMemorySize,
                         (int)SMEM_BYTES);

    prepack<<<PRE4N / 256, 256>>>(q, k, v);
    anomaly_mma<<<NBATCH * NHEAD * 32, 256, SMEM_BYTES>>>(sg, out);
}

// round 15
// speedup vs baseline: 1.5161x; 1.0359x over previous
#include <cuda_runtime.h>
#include <cuda_fp16.h>
#include <math.h>
#include <stdint.h>

#define NBATCH 32
#define NHEAD  8
#define SEQ    512
#define HD     64

constexpr size_t V_SIZE   = (size_t)NBATCH * SEQ * NHEAD * HD;     // 8388608
constexpr size_t SER_SIZE = (size_t)NBATCH * NHEAD * SEQ * SEQ;    // 67108864

// ---- prepacked fp16 fragment arrays (fragment-major, rne-rounded) ----
__device__ uint4 d_KB[(size_t)256 * 64 * 2 * 32];
__device__ uint4 d_VB[(size_t)256 * 8 * 4 * 4 * 32];
__device__ uint4 d_QA[(size_t)256 * 32 * 4 * 32];

constexpr int KB4N = 256 * 64 * 2 * 32;
constexpr int VB4N = 256 * 8 * 4 * 4 * 32;
constexpr int QA4N = 256 * 32 * 4 * 32;
constexpr int PRE4N = KB4N + VB4N + QA4N;

// ---- smem layout (bytes) ----
// A: per-warp 4KB double buffer (K loop1 / V loop2)
// B: per-warp fp16 P stash, uint32[16][36] = 2304B; reused as fp32 V-partials [16][32]
constexpr uint32_t A_OFF   = 0;        // 8 * 4096 = 32768
constexpr uint32_t B_OFF   = 32768;
constexpr uint32_t STASH_W = 2304;     // 16 * 36 * 4
constexpr uint32_t RS_OFF  = B_OFF + 8 * STASH_W;   // 51200
constexpr uint32_t INV_OFF = RS_OFF + 512;          // 51712
constexpr uint32_t SMEM_BYTES = INV_OFF + 64;       // 51776

__device__ __forceinline__ uint32_t s2u(const void* p) {
    uint32_t a;
    asm("{ .reg .u64 t; cvta.to.shared.u64 t, %1; cvt.u32.u64 %0, t; }" : "=r"(a) : "l"(p));
    return a;
}
__device__ __forceinline__ void cp16(uint32_t dst, const void* src) {
    asm volatile("cp.async.cg.shared.global [%0], [%1], 16;" :: "r"(dst), "l"(src) : "memory");
}
__device__ __forceinline__ void cpcommit() { asm volatile("cp.async.commit_group;" ::: "memory"); }
__device__ __forceinline__ void cpwait0()  { asm volatile("cp.async.wait_group 0;" ::: "memory"); }
__device__ __forceinline__ void cpwait1()  { asm volatile("cp.async.wait_group 1;" ::: "memory"); }

__device__ __forceinline__ uint32_t h2(float x, float y) {
    __half2 v = __floats2half2_rn(x, y);
    return *(uint32_t*)&v;
}

__device__ __forceinline__ void mma_f16(float* c, const uint32_t* a, uint32_t b0, uint32_t b1) {
    asm volatile(
        "mma.sync.aligned.m16n8k16.row.col.f32.f16.f16.f32 "
        "{%0,%1,%2,%3},{%4,%5,%6,%7},{%8,%9},{%0,%1,%2,%3};\n"
        : "+f"(c[0]), "+f"(c[1]), "+f"(c[2]), "+f"(c[3])
        : "r"(a[0]), "r"(a[1]), "r"(a[2]), "r"(a[3]), "r"(b0), "r"(b1));
}

// ---------------- prepack (unchanged from round 13/14) ----------------
__global__ void __launch_bounds__(256) prepack(const float* __restrict__ Q,
                                               const float* __restrict__ K,
                                               const float* __restrict__ V) {
    int idx = blockIdx.x * 256 + threadIdx.x;
    int lane = idx & 31, g = (lane >> 2), t = lane & 3;
    if (idx < KB4N) {
        int c = (idx >> 5) & 1, st = (idx >> 6) & 63, bh = idx >> 12;
        int b = bh >> 3, h = bh & 7;
        int s = st * 8 + g;
        const float* kp = K + (((size_t)b * SEQ + s) * NHEAD + h) * HD;
        int ka = (2 * c) * 16 + 2 * t;
        int kb = (2 * c + 1) * 16 + 2 * t;
        d_KB[idx] = make_uint4(h2(kp[ka], kp[ka + 1]), h2(kp[ka + 8], kp[ka + 9]),
                               h2(kp[kb], kp[kb + 1]), h2(kp[kb + 8], kp[kb + 9]));
    } else if (idx < KB4N + VB4N) {
        int i = idx - KB4N;
        int j = (i >> 5) & 3, k2 = (i >> 7) & 3, cq = (i >> 9) & 7, bh = i >> 12;
        int b = bh >> 3, h = bh & 7;
        int s0 = cq * 64 + k2 * 16;
        int d0 = (2 * j) * 8 + g, d1 = (2 * j + 1) * 8 + g;
        const float* vp = V + ((size_t)b * SEQ * NHEAD + h) * HD;
        d_VB[i] = make_uint4(
            h2(vp[(size_t)(s0 + 2 * t) * 512 + d0],     vp[(size_t)(s0 + 2 * t + 1) * 512 + d0]),
            h2(vp[(size_t)(s0 + 2 * t + 8) * 512 + d0], vp[(size_t)(s0 + 2 * t + 9) * 512 + d0]),
            h2(vp[(size_t)(s0 + 2 * t) * 512 + d1],     vp[(size_t)(s0 + 2 * t + 1) * 512 + d1]),
            h2(vp[(size_t)(s0 + 2 * t + 8) * 512 + d1], vp[(size_t)(s0 + 2 * t + 9) * 512 + d1]));
    } else if (idx < PRE4N) {
        int i = idx - KB4N - VB4N;
        int kt = (i >> 5) & 3, rt = (i >> 7) & 31, bh = i >> 12;
        int b = bh >> 3, h = bh & 7;
        int k0 = kt * 16 + 2 * t;
        const float* qp = Q + (((size_t)b * SEQ + rt * 16) * NHEAD + h) * HD;
        d_QA[i] = make_uint4(
            h2(qp[(size_t)g * 512 + k0],           qp[(size_t)g * 512 + k0 + 1]),
            h2(qp[(size_t)(g + 8) * 512 + k0],     qp[(size_t)(g + 8) * 512 + k0 + 1]),
            h2(qp[(size_t)g * 512 + k0 + 8],       qp[(size_t)g * 512 + k0 + 9]),
            h2(qp[(size_t)(g + 8) * 512 + k0 + 8], qp[(size_t)(g + 8) * 512 + k0 + 9]));
    }
}

// ---------------- main ----------------
// CTA: 16 rows x 512 cols. loop1: 8 warps = 8 col-slices of 64.
// loop2: warp = (sh, dh); fp16 P stash (uint32 stride 36, conflict-free).
__global__ void __launch_bounds__(256, 3) anomaly_mma(const float* __restrict__ SG,
                                                      float* __restrict__ out) {
    extern __shared__ char sm[];
    const uint32_t smb = s2u(sm);
    float* RS  = (float*)(sm + RS_OFF);
    float* INV = (float*)(sm + INV_OFF);

    const int tid = threadIdx.x, lane = tid & 31, wid = tid >> 5;
    const int g = lane >> 2, t = lane & 3;
    const int mt = blockIdx.x & 31;
    const int bh = blockIdx.x >> 5;
    const int h = bh & 7, b = bh >> 3;
    const int l0 = mt * 16;
    const int cq = wid;

    const uint32_t Aw = smb + A_OFF + wid * 4096;
    char* Awc = sm + A_OFF + wid * 4096;
    uint32_t* stgu = (uint32_t*)(sm + B_OFF + wid * STASH_W);   // [16][36] half2

    const char* srcK = (const char*)d_KB + (size_t)(bh * 64 + cq * 8) * 1024;

    // prologue: K k2=0 (stiles 0,1) into buffer 0
    #pragma unroll
    for (int n = 0; n < 2; n++)
        #pragma unroll
        for (int c = 0; c < 2; c++)
            cp16(Aw + n * 1024 + c * 512 + lane * 16,
                 srcK + (size_t)n * 1024 + c * 512 + lane * 16);
    cpcommit();

    // ---- Q fragments (fp16) ----
    uint32_t qa[4][4];
    {
        const uint4* qp4 = d_QA + ((size_t)(bh * 32 + mt) * 4) * 32 + lane;
        #pragma unroll
        for (int kt = 0; kt < 4; kt++) {
            uint4 v = qp4[kt * 32];
            qa[kt][0] = v.x; qa[kt][1] = v.y; qa[kt][2] = v.z; qa[kt][3] = v.w;
        }
    }

    // ================= loop1: GEMM1 (fp16) -> exp -> fp16 stash =================
    float rs0 = 0.f, rs1 = 0.f;
    #pragma unroll
    for (int k2 = 0; k2 < 4; k2++) {
        if (k2 < 3) {
            const int nb = (k2 + 1) & 1;
            #pragma unroll
            for (int n = 0; n < 2; n++)
                #pragma unroll
                for (int c = 0; c < 2; c++)
                    cp16(Aw + nb * 2048 + n * 1024 + c * 512 + lane * 16,
                         srcK + (size_t)(2 * (k2 + 1) + n) * 1024 + c * 512 + lane * 16);
            cpcommit();
            cpwait1();
        } else {
            cpwait0();
        }

        const char* kb = Awc + (k2 & 1) * 2048;
        float aA[2][4], aB[2][4];
        #pragma unroll
        for (int n = 0; n < 2; n++)
            #pragma unroll
            for (int r = 0; r < 4; r++) { aA[n][r] = 0.f; aB[n][r] = 0.f; }

        #pragma unroll
        for (int n = 0; n < 2; n++) {
            uint4 X = *(const uint4*)(kb + n * 1024 + lane * 16);
            uint4 Y = *(const uint4*)(kb + n * 1024 + 512 + lane * 16);
            mma_f16(aA[n], qa[0], X.x, X.y);
            mma_f16(aB[n], qa[1], X.z, X.w);
            mma_f16(aA[n], qa[2], Y.x, Y.y);
            mma_f16(aB[n], qa[3], Y.z, Y.w);
        }

        float p[2][4];
        #pragma unroll
        for (int n = 0; n < 2; n++)
            #pragma unroll
            for (int r = 0; r < 4; r++)
                p[n][r] = __expf(0.125f * (aA[n][r] + aB[n][r]));

        rs0 += p[0][0] + p[0][1] + p[1][0] + p[1][1];
        rs1 += p[0][2] + p[0][3] + p[1][2] + p[1][3];

        // fp16 stash: u32 col = k2*8 + n*4 + t; rows g, g+8 (bank 4g+t: conflict-free)
        stgu[g * 36 + k2 * 8 + t]            = h2(p[0][0], p[0][1]);
        stgu[g * 36 + k2 * 8 + 4 + t]        = h2(p[1][0], p[1][1]);
        stgu[(g + 8) * 36 + k2 * 8 + t]      = h2(p[0][2], p[0][3]);
        stgu[(g + 8) * 36 + k2 * 8 + 4 + t]  = h2(p[1][2], p[1][3]);
    }

    // ---- loop2 warp roles + V prologue prefetch (overlaps rowsum barrier) ----
    const int sh = wid >> 1;
    const int dh = wid & 1;
    const char* srcV0 = (const char*)d_VB +
        ((((size_t)(bh * 8 + 2 * sh) * 4 + 0) * 4 + 2 * dh) * 32) * 16;
    cp16(Aw + lane * 16,       srcV0 + lane * 16);
    cp16(Aw + 512 + lane * 16, srcV0 + 512 + lane * 16);
    cpcommit();

    // ---- rowsums -> inv ----
    rs0 += __shfl_xor_sync(0xffffffffu, rs0, 1);
    rs0 += __shfl_xor_sync(0xffffffffu, rs0, 2);
    rs1 += __shfl_xor_sync(0xffffffffu, rs1, 1);
    rs1 += __shfl_xor_sync(0xffffffffu, rs1, 2);
    if (t == 0) {
        RS[g * 8 + wid]       = rs0;
        RS[(g + 8) * 8 + wid] = rs1;
    }
    __syncthreads();   // publishes stash for cross-warp loop2 reads
    if (tid < 16) {
        float s = 0.f;
        #pragma unroll
        for (int w = 0; w < 8; w++) s += RS[tid * 8 + w];
        INV[tid] = 1.0f / s;
    }
    __syncthreads();
    const float invg  = INV[g];
    const float invg8 = INV[g + 8];

    // ================= loop2: GEMM2 (fp16), A-frags raw from fp16 stash =================
    float vacc[4][4];
    #pragma unroll
    for (int j = 0; j < 4; j++)
        #pragma unroll
        for (int r = 0; r < 4; r++) vacc[j][r] = 0.f;

    #pragma unroll
    for (int st = 0; st < 8; st++) {
        if (st < 7) {
            const int stn = st + 1;
            const char* srcn = (const char*)d_VB +
                ((((size_t)(bh * 8 + 2 * sh + (stn >> 2)) * 4 + (stn & 3)) * 4 + 2 * dh) * 32) * 16;
            const uint32_t dstb = Aw + (stn & 1) * 1024;
            cp16(dstb + lane * 16,       srcn + lane * 16);
            cp16(dstb + 512 + lane * 16, srcn + 512 + lane * 16);
            cpcommit();
            cpwait1();
        } else {
            cpwait0();
        }

        const uint32_t* stq = (const uint32_t*)(sm + B_OFF + (2 * sh + (st >> 2)) * STASH_W);
        const int c0 = (st & 3) * 8;
        uint32_t ua[4];
        ua[0] = stq[g * 36 + c0 + t];
        ua[1] = stq[(g + 8) * 36 + c0 + t];
        ua[2] = stq[g * 36 + c0 + 4 + t];
        ua[3] = stq[(g + 8) * 36 + c0 + 4 + t];

        const char* vb = Awc + (st & 1) * 1024;
        uint4 B0 = *(const uint4*)(vb + lane * 16);
        uint4 B1 = *(const uint4*)(vb + 512 + lane * 16);
        mma_f16(vacc[0], ua, B0.x, B0.y);
        mma_f16(vacc[1], ua, B0.z, B0.w);
        mma_f16(vacc[2], ua, B1.x, B1.y);
        mma_f16(vacc[3], ua, B1.z, B1.w);
    }

    // ---- series write pass: coalesced; unpack fp16 stash ----
    {
        float* ser = out + V_SIZE + ((size_t)bh * 512 + l0) * 512 + cq * 64;
        #pragma unroll
        for (int r = 0; r < 16; r++) {
            uint32_t u = stgu[r * 36 + lane];
            float2 f = __half22float2(*(__half2*)&u);
            const float iv = INV[r];
            __stcs((float2*)(ser + (size_t)r * 512 + lane * 2),
                   make_float2(f.x * iv, f.y * iv));
        }
    }

    // ---- V cross-warp reduction (4 partials per (row,d)) ----
    __syncthreads();   // all warps done reading stashes (loop2 cross-warp + series)
    {
        float* part = (float*)stgu;   // [16 rows][32 d-local] = 2048B <= 2304B
        #pragma unroll
        for (int j = 0; j < 4; j++) {
            part[g * 32 + j * 8 + 2 * t]           = vacc[j][0] * invg;
            part[g * 32 + j * 8 + 2 * t + 1]       = vacc[j][1] * invg;
            part[(g + 8) * 32 + j * 8 + 2 * t]     = vacc[j][2] * invg8;
            part[(g + 8) * 32 + j * 8 + 2 * t + 1] = vacc[j][3] * invg8;
        }
        __syncthreads();
        const int d = tid & 63;
        const int dv = d & 31, wsel = d >> 5;
        #pragma unroll
        for (int it = 0; it < 4; it++) {
            const int row = (tid >> 6) + it * 4;
            float s = 0.f;
            #pragma unroll
            for (int shh = 0; shh < 4; shh++)
                s += ((float*)(sm + B_OFF + (shh * 2 + wsel) * STASH_W))[row * 32 + dv];
            __stcs(out + (((size_t)b * SEQ + l0 + row) * NHEAD + h) * HD + d, s);
        }
    }

    // ---- prior: warp sweeps 128-col chunks, lane*4 contiguous; warp-uniform skip ----
    {
        float amp_ = 0.f, ninv_ = 0.f;
        if (lane < 2) {
            int l = l0 + wid * 2 + lane;
            float x   = SG[((size_t)b * SEQ + l) * NHEAD + h];
            float smv = 1.0f / (1.0f + __expf(-5.0f * x));
            float yf  = smv + 1e-5f;
            float p3  = (float)exp((double)yf * 1.0986122886681098);
            float sig = p3 - 1.0f;
            amp_  = 0.3989422804014327f / sig;
            ninv_ = -1.0f / (2.0f * sig * sig);
        }
        float* priorBase = out + V_SIZE + SER_SIZE + ((size_t)bh * 512 + l0) * 512;
        #pragma unroll
        for (int rr = 0; rr < 2; rr++) {
            const float amp  = __shfl_sync(0xffffffffu, amp_, rr);
            const float ninv = __shfl_sync(0xffffffffu, ninv_, rr);
            const int l = l0 + wid * 2 + rr;
            float* pp = priorBase + (size_t)(wid * 2 + rr) * 512;
            #pragma unroll
            for (int j = 0; j < 4; j++) {
                const int c0 = j * 128;
                int dhh = l - c0, dll = l - (c0 + 127);
                int admin = (dll <= 0 && dhh >= 0) ? 0 : min(abs(dll), abs(dhh));
                float* dst = pp + c0 + lane * 4;
                if (ninv * (float)(admin * admin) < -87.0f) {
                    __stcs((float4*)dst, make_float4(0.f, 0.f, 0.f, 0.f));
                } else {
                    const int s = c0 + lane * 4;
                    float d0 = (float)(l - s);
                    float d1 = (float)(l - (s + 1));
                    float d2 = (float)(l - (s + 2));
                    float d3 = (float)(l - (s + 3));
                    float4 o;
                    o.x = amp * __expf(ninv * d0 * d0);
                    o.y = amp * __expf(ninv * d1 * d1);
                    o.z = amp * __expf(ninv * d2 * d2);
                    o.w = amp * __expf(ninv * d3 * d3);
                    __stcs((float4*)dst, o);
                }
            }
        }
    }
}

extern "C" void kernel_launch(void* const* d_in, const int* in_sizes, int n_in,
                              void* d_out, int out_size) {
    (void)in_sizes; (void)n_in; (void)out_size;
    const float* q  = (const float*)d_in[0];
    const float* k  = (const float*)d_in[1];
    const float* v  = (const float*)d_in[2];
    const float* sg = (const float*)d_in[3];
    float* out = (float*)d_out;

    cudaFuncSetAttribute(anomaly_mma, cudaFuncAttributeMaxDynamicSharedMemorySize,
                         (int)SMEM_BYTES);

    prepack<<<PRE4N / 256, 256>>>(q, k, v);
    anomaly_mma<<<NBATCH * NHEAD * 32, 256, SMEM_BYTES>>>(sg, out);
}

// round 16
// speedup vs baseline: 1.6328x; 1.0770x over previous
#include <cuda_runtime.h>
#include <cuda_fp16.h>
#include <math.h>
#include <stdint.h>

#define NBATCH 32
#define NHEAD  8
#define SEQ    512
#define HD     64

constexpr size_t V_SIZE   = (size_t)NBATCH * SEQ * NHEAD * HD;     // 8388608
constexpr size_t SER_SIZE = (size_t)NBATCH * NHEAD * SEQ * SEQ;    // 67108864

// ---- prepacked fp16 fragment arrays (fragment-major, rne-rounded) ----
__device__ uint4 d_KB[(size_t)256 * 64 * 2 * 32];
__device__ uint4 d_VB[(size_t)256 * 8 * 4 * 4 * 32];
__device__ uint4 d_QA[(size_t)256 * 32 * 4 * 32];

constexpr int KB4N = 256 * 64 * 2 * 32;
constexpr int VB4N = 256 * 8 * 4 * 4 * 32;
constexpr int QA4N = 256 * 32 * 4 * 32;
constexpr int PRE4N = KB4N + VB4N + QA4N;

// ---- smem layout (bytes) ----
// A: per-warp 6KB TRIPLE buffer (loop1: 3 x 2KB k2-granules; loop2: 3 x 1KB st-granules)
// B: per-warp fp16 P stash, uint32[16][36] = 2304B; reused as fp32 V-partials [16][32]
constexpr uint32_t A_OFF   = 0;                     // 8 * 6144 = 49152
constexpr uint32_t AW_SZ   = 6144;
constexpr uint32_t B_OFF   = 49152;
constexpr uint32_t STASH_W = 2304;
constexpr uint32_t RS_OFF  = B_OFF + 8 * STASH_W;   // 67584
constexpr uint32_t INV_OFF = RS_OFF + 512;          // 68096
constexpr uint32_t SMEM_BYTES = INV_OFF + 64;       // 68160  (x3 = 204KB <= 228KB)

__device__ __forceinline__ uint32_t s2u(const void* p) {
    uint32_t a;
    asm("{ .reg .u64 t; cvta.to.shared.u64 t, %1; cvt.u32.u64 %0, t; }" : "=r"(a) : "l"(p));
    return a;
}
__device__ __forceinline__ void cp16(uint32_t dst, const void* src) {
    asm volatile("cp.async.cg.shared.global [%0], [%1], 16;" :: "r"(dst), "l"(src) : "memory");
}
__device__ __forceinline__ void cpcommit() { asm volatile("cp.async.commit_group;" ::: "memory"); }
__device__ __forceinline__ void cpwait0()  { asm volatile("cp.async.wait_group 0;" ::: "memory"); }
__device__ __forceinline__ void cpwait1()  { asm volatile("cp.async.wait_group 1;" ::: "memory"); }
__device__ __forceinline__ void cpwait2()  { asm volatile("cp.async.wait_group 2;" ::: "memory"); }

__device__ __forceinline__ uint32_t h2(float x, float y) {
    __half2 v = __floats2half2_rn(x, y);
    return *(uint32_t*)&v;
}

__device__ __forceinline__ void mma_f16(float* c, const uint32_t* a, uint32_t b0, uint32_t b1) {
    asm volatile(
        "mma.sync.aligned.m16n8k16.row.col.f32.f16.f16.f32 "
        "{%0,%1,%2,%3},{%4,%5,%6,%7},{%8,%9},{%0,%1,%2,%3};\n"
        : "+f"(c[0]), "+f"(c[1]), "+f"(c[2]), "+f"(c[3])
        : "r"(a[0]), "r"(a[1]), "r"(a[2]), "r"(a[3]), "r"(b0), "r"(b1));
}

// ---------------- prepack (unchanged) ----------------
__global__ void __launch_bounds__(256) prepack(const float* __restrict__ Q,
                                               const float* __restrict__ K,
                                               const float* __restrict__ V) {
    int idx = blockIdx.x * 256 + threadIdx.x;
    int lane = idx & 31, g = (lane >> 2), t = lane & 3;
    if (idx < KB4N) {
        int c = (idx >> 5) & 1, st = (idx >> 6) & 63, bh = idx >> 12;
        int b = bh >> 3, h = bh & 7;
        int s = st * 8 + g;
        const float* kp = K + (((size_t)b * SEQ + s) * NHEAD + h) * HD;
        int ka = (2 * c) * 16 + 2 * t;
        int kb = (2 * c + 1) * 16 + 2 * t;
        d_KB[idx] = make_uint4(h2(kp[ka], kp[ka + 1]), h2(kp[ka + 8], kp[ka + 9]),
                               h2(kp[kb], kp[kb + 1]), h2(kp[kb + 8], kp[kb + 9]));
    } else if (idx < KB4N + VB4N) {
        int i = idx - KB4N;
        int j = (i >> 5) & 3, k2 = (i >> 7) & 3, cq = (i >> 9) & 7, bh = i >> 12;
        int b = bh >> 3, h = bh & 7;
        int s0 = cq * 64 + k2 * 16;
        int d0 = (2 * j) * 8 + g, d1 = (2 * j + 1) * 8 + g;
        const float* vp = V + ((size_t)b * SEQ * NHEAD + h) * HD;
        d_VB[i] = make_uint4(
            h2(vp[(size_t)(s0 + 2 * t) * 512 + d0],     vp[(size_t)(s0 + 2 * t + 1) * 512 + d0]),
            h2(vp[(size_t)(s0 + 2 * t + 8) * 512 + d0], vp[(size_t)(s0 + 2 * t + 9) * 512 + d0]),
            h2(vp[(size_t)(s0 + 2 * t) * 512 + d1],     vp[(size_t)(s0 + 2 * t + 1) * 512 + d1]),
            h2(vp[(size_t)(s0 + 2 * t + 8) * 512 + d1], vp[(size_t)(s0 + 2 * t + 9) * 512 + d1]));
    } else if (idx < PRE4N) {
        int i = idx - KB4N - VB4N;
        int kt = (i >> 5) & 3, rt = (i >> 7) & 31, bh = i >> 12;
        int b = bh >> 3, h = bh & 7;
        int k0 = kt * 16 + 2 * t;
        const float* qp = Q + (((size_t)b * SEQ + rt * 16) * NHEAD + h) * HD;
        d_QA[i] = make_uint4(
            h2(qp[(size_t)g * 512 + k0],           qp[(size_t)g * 512 + k0 + 1]),
            h2(qp[(size_t)(g + 8) * 512 + k0],     qp[(size_t)(g + 8) * 512 + k0 + 1]),
            h2(qp[(size_t)g * 512 + k0 + 8],       qp[(size_t)g * 512 + k0 + 9]),
            h2(qp[(size_t)(g + 8) * 512 + k0 + 8], qp[(size_t)(g + 8) * 512 + k0 + 9]));
    }
}

// ---------------- main ----------------
// CTA: 16 rows x 512 cols. loop1: 8 warps = 8 col-slices. loop2: warp = (sh, dh).
// Triple-buffered cp.async (2 groups in flight) to cover L2+smem latency.
__global__ void __launch_bounds__(256, 3) anomaly_mma(const float* __restrict__ SG,
                                                      float* __restrict__ out) {
    extern __shared__ char sm[];
    const uint32_t smb = s2u(sm);
    float* RS  = (float*)(sm + RS_OFF);
    float* INV = (float*)(sm + INV_OFF);

    const int tid = threadIdx.x, lane = tid & 31, wid = tid >> 5;
    const int g = lane >> 2, t = lane & 3;
    const int mt = blockIdx.x & 31;
    const int bh = blockIdx.x >> 5;
    const int h = bh & 7, b = bh >> 3;
    const int l0 = mt * 16;
    const int cq = wid;

    const uint32_t Aw = smb + A_OFF + wid * AW_SZ;
    char* Awc = sm + A_OFF + wid * AW_SZ;
    uint32_t* stgu = (uint32_t*)(sm + B_OFF + wid * STASH_W);

    const char* srcK = (const char*)d_KB + (size_t)(bh * 64 + cq * 8) * 1024;

    // prologue: issue K k2=0 and k2=1 (2 groups in flight)
    #pragma unroll
    for (int kk = 0; kk < 2; kk++) {
        #pragma unroll
        for (int n = 0; n < 2; n++)
            #pragma unroll
            for (int c = 0; c < 2; c++)
                cp16(Aw + kk * 2048 + n * 1024 + c * 512 + lane * 16,
                     srcK + (size_t)(2 * kk + n) * 1024 + c * 512 + lane * 16);
        cpcommit();
    }

    // ---- Q fragments (fp16) ----
    uint32_t qa[4][4];
    {
        const uint4* qp4 = d_QA + ((size_t)(bh * 32 + mt) * 4) * 32 + lane;
        #pragma unroll
        for (int kt = 0; kt < 4; kt++) {
            uint4 v = qp4[kt * 32];
            qa[kt][0] = v.x; qa[kt][1] = v.y; qa[kt][2] = v.z; qa[kt][3] = v.w;
        }
    }

    // ================= loop1: GEMM1 (fp16) -> exp -> fp16 stash =================
    float rs0 = 0.f, rs1 = 0.f;
    #pragma unroll
    for (int k2 = 0; k2 < 4; k2++) {
        if (k2 < 2) {
            const int kn = k2 + 2;                 // buffer kn % 3
            const uint32_t dstb = Aw + (kn % 3) * 2048;
            #pragma unroll
            for (int n = 0; n < 2; n++)
                #pragma unroll
                for (int c = 0; c < 2; c++)
                    cp16(dstb + n * 1024 + c * 512 + lane * 16,
                         srcK + (size_t)(2 * kn + n) * 1024 + c * 512 + lane * 16);
            cpcommit();
        }
        if (k2 <= 1)      cpwait2();
        else if (k2 == 2) cpwait1();
        else              cpwait0();

        const char* kb = Awc + (k2 % 3) * 2048;
        float aA[2][4], aB[2][4];
        #pragma unroll
        for (int n = 0; n < 2; n++)
            #pragma unroll
            for (int r = 0; r < 4; r++) { aA[n][r] = 0.f; aB[n][r] = 0.f; }

        #pragma unroll
        for (int n = 0; n < 2; n++) {
            uint4 X = *(const uint4*)(kb + n * 1024 + lane * 16);
            uint4 Y = *(const uint4*)(kb + n * 1024 + 512 + lane * 16);
            mma_f16(aA[n], qa[0], X.x, X.y);
            mma_f16(aB[n], qa[1], X.z, X.w);
            mma_f16(aA[n], qa[2], Y.x, Y.y);
            mma_f16(aB[n], qa[3], Y.z, Y.w);
        }

        float p[2][4];
        #pragma unroll
        for (int n = 0; n < 2; n++)
            #pragma unroll
            for (int r = 0; r < 4; r++)
                p[n][r] = __expf(0.125f * (aA[n][r] + aB[n][r]));

        rs0 += p[0][0] + p[0][1] + p[1][0] + p[1][1];
        rs1 += p[0][2] + p[0][3] + p[1][2] + p[1][3];

        stgu[g * 36 + k2 * 8 + t]            = h2(p[0][0], p[0][1]);
        stgu[g * 36 + k2 * 8 + 4 + t]        = h2(p[1][0], p[1][1]);
        stgu[(g + 8) * 36 + k2 * 8 + t]      = h2(p[0][2], p[0][3]);
        stgu[(g + 8) * 36 + k2 * 8 + 4 + t]  = h2(p[1][2], p[1][3]);
    }

    // ---- loop2 warp roles + V prologue: issue st=0 AND st=1 before barrier ----
    const int sh = wid >> 1;
    const int dh = wid & 1;
    #pragma unroll
    for (int ss = 0; ss < 2; ss++) {
        const char* srcs = (const char*)d_VB +
            ((((size_t)(bh * 8 + 2 * sh + (ss >> 2)) * 4 + (ss & 3)) * 4 + 2 * dh) * 32) * 16;
        const uint32_t dstb = Aw + ss * 1024;
        cp16(dstb + lane * 16,       srcs + lane * 16);
        cp16(dstb + 512 + lane * 16, srcs + 512 + lane * 16);
        cpcommit();
    }

    // ---- rowsums -> inv ----
    rs0 += __shfl_xor_sync(0xffffffffu, rs0, 1);
    rs0 += __shfl_xor_sync(0xffffffffu, rs0, 2);
    rs1 += __shfl_xor_sync(0xffffffffu, rs1, 1);
    rs1 += __shfl_xor_sync(0xffffffffu, rs1, 2);
    if (t == 0) {
        RS[g * 8 + wid]       = rs0;
        RS[(g + 8) * 8 + wid] = rs1;
    }
    __syncthreads();   // publishes stash for cross-warp loop2 reads
    if (tid < 16) {
        float s = 0.f;
        #pragma unroll
        for (int w = 0; w < 8; w++) s += RS[tid * 8 + w];
        INV[tid] = 1.0f / s;
    }
    __syncthreads();
    const float invg  = INV[g];
    const float invg8 = INV[g + 8];

    // ================= loop2: GEMM2 (fp16), triple-buffered V =================
    float vacc[4][4];
    #pragma unroll
    for (int j = 0; j < 4; j++)
        #pragma unroll
        for (int r = 0; r < 4; r++) vacc[j][r] = 0.f;

    #pragma unroll
    for (int st = 0; st < 8; st++) {
        if (st < 6) {
            const int stn = st + 2;
            const char* srcn = (const char*)d_VB +
                ((((size_t)(bh * 8 + 2 * sh + (stn >> 2)) * 4 + (stn & 3)) * 4 + 2 * dh) * 32) * 16;
            const uint32_t dstb = Aw + (stn % 3) * 1024;
            cp16(dstb + lane * 16,       srcn + lane * 16);
            cp16(dstb + 512 + lane * 16, srcn + 512 + lane * 16);
            cpcommit();
        }
        if (st < 6)       cpwait2();
        else if (st == 6) cpwait1();
        else              cpwait0();

        const uint32_t* stq = (const uint32_t*)(sm + B_OFF + (2 * sh + (st >> 2)) * STASH_W);
        const int c0 = (st & 3) * 8;
        uint32_t ua[4];
        ua[0] = stq[g * 36 + c0 + t];
        ua[1] = stq[(g + 8) * 36 + c0 + t];
        ua[2] = stq[g * 36 + c0 + 4 + t];
        ua[3] = stq[(g + 8) * 36 + c0 + 4 + t];

        const char* vb = Awc + (st % 3) * 1024;
        uint4 B0 = *(const uint4*)(vb + lane * 16);
        uint4 B1 = *(const uint4*)(vb + 512 + lane * 16);
        mma_f16(vacc[0], ua, B0.x, B0.y);
        mma_f16(vacc[1], ua, B0.z, B0.w);
        mma_f16(vacc[2], ua, B1.x, B1.y);
        mma_f16(vacc[3], ua, B1.z, B1.w);
    }

    // ---- series write pass: coalesced; unpack fp16 stash ----
    {
        float* ser = out + V_SIZE + ((size_t)bh * 512 + l0) * 512 + cq * 64;
        #pragma unroll
        for (int r = 0; r < 16; r++) {
            uint32_t u = stgu[r * 36 + lane];
            float2 f = __half22float2(*(__half2*)&u);
            const float iv = INV[r];
            __stcs((float2*)(ser + (size_t)r * 512 + lane * 2),
                   make_float2(f.x * iv, f.y * iv));
        }
    }

    // ---- V cross-warp reduction (4 partials per (row,d)) ----
    __syncthreads();   // all warps done reading stashes (loop2 cross-warp + series)
    {
        float* part = (float*)stgu;   // [16 rows][32 d-local] = 2048B <= 2304B
        #pragma unroll
        for (int j = 0; j < 4; j++) {
            part[g * 32 + j * 8 + 2 * t]           = vacc[j][0] * invg;
            part[g * 32 + j * 8 + 2 * t + 1]       = vacc[j][1] * invg;
            part[(g + 8) * 32 + j * 8 + 2 * t]     = vacc[j][2] * invg8;
            part[(g + 8) * 32 + j * 8 + 2 * t + 1] = vacc[j][3] * invg8;
        }
        __syncthreads();
        const int d = tid & 63;
        const int dv = d & 31, wsel = d >> 5;
        #pragma unroll
        for (int it = 0; it < 4; it++) {
            const int row = (tid >> 6) + it * 4;
            float s = 0.f;
            #pragma unroll
            for (int shh = 0; shh < 4; shh++)
                s += ((float*)(sm + B_OFF + (shh * 2 + wsel) * STASH_W))[row * 32 + dv];
            __stcs(out + (((size_t)b * SEQ + l0 + row) * NHEAD + h) * HD + d, s);
        }
    }

    // ---- prior: warp sweeps 128-col chunks, lane*4 contiguous; warp-uniform skip ----
    {
        float amp_ = 0.f, ninv_ = 0.f;
        if (lane < 2) {
            int l = l0 + wid * 2 + lane;
            float x   = SG[((size_t)b * SEQ + l) * NHEAD + h];
            float smv = 1.0f / (1.0f + __expf(-5.0f * x));
            float yf  = smv + 1e-5f;
            float p3  = (float)exp((double)yf * 1.0986122886681098);
            float sig = p3 - 1.0f;
            amp_  = 0.3989422804014327f / sig;
            ninv_ = -1.0f / (2.0f * sig * sig);
        }
        float* priorBase = out + V_SIZE + SER_SIZE + ((size_t)bh * 512 + l0) * 512;
        #pragma unroll
        for (int rr = 0; rr < 2; rr++) {
            const float amp  = __shfl_sync(0xffffffffu, amp_, rr);
            const float ninv = __shfl_sync(0xffffffffu, ninv_, rr);
            const int l = l0 + wid * 2 + rr;
            float* pp = priorBase + (size_t)(wid * 2 + rr) * 512;
            #pragma unroll
            for (int j = 0; j < 4; j++) {
                const int c0 = j * 128;
                int dhh = l - c0, dll = l - (c0 + 127);
                int admin = (dll <= 0 && dhh >= 0) ? 0 : min(abs(dll), abs(dhh));
                float* dst = pp + c0 + lane * 4;
                if (ninv * (float)(admin * admin) < -87.0f) {
                    __stcs((float4*)dst, make_float4(0.f, 0.f, 0.f, 0.f));
                } else {
                    const int s = c0 + lane * 4;
                    float d0 = (float)(l - s);
                    float d1 = (float)(l - (s + 1));
                    float d2 = (float)(l - (s + 2));
                    float d3 = (float)(l - (s + 3));
                    float4 o;
                    o.x = amp * __expf(ninv * d0 * d0);
                    o.y = amp * __expf(ninv * d1 * d1);
                    o.z = amp * __expf(ninv * d2 * d2);
                    o.w = amp * __expf(ninv * d3 * d3);
                    __stcs((float4*)dst, o);
                }
            }
        }
    }
}

extern "C" void kernel_launch(void* const* d_in, const int* in_sizes, int n_in,
                              void* d_out, int out_size) {
    (void)in_sizes; (void)n_in; (void)out_size;
    const float* q  = (const float*)d_in[0];
    const float* k  = (const float*)d_in[1];
    const float* v  = (const float*)d_in[2];
    const float* sg = (const float*)d_in[3];
    float* out = (float*)d_out;

    cudaFuncSetAttribute(anomaly_mma, cudaFuncAttributeMaxDynamicSharedMemorySize,
                         (int)SMEM_BYTES);

    prepack<<<PRE4N / 256, 256>>>(q, k, v);
    anomaly_mma<<<NBATCH * NHEAD * 32, 256, SMEM_BYTES>>>(sg, out);
}

// round 17
// speedup vs baseline: 1.7476x; 1.0703x over previous
#include <cuda_runtime.h>
#include <cuda_fp16.h>
#include <math.h>
#include <stdint.h>

#define NBATCH 32
#define NHEAD  8
#define SEQ    512
#define HD     64

constexpr size_t V_SIZE   = (size_t)NBATCH * SEQ * NHEAD * HD;     // 8388608
constexpr size_t SER_SIZE = (size_t)NBATCH * NHEAD * SEQ * SEQ;    // 67108864

// ---- prepacked fp16 fragment arrays (fragment-major, rne-rounded) ----
__device__ uint4 d_KB[(size_t)256 * 64 * 2 * 32];
__device__ uint4 d_VB[(size_t)256 * 8 * 4 * 4 * 32];
__device__ uint4 d_QA[(size_t)256 * 32 * 4 * 32];

constexpr int KB4N = 256 * 64 * 2 * 32;
constexpr int VB4N = 256 * 8 * 4 * 4 * 32;
constexpr int QA4N = 256 * 32 * 4 * 32;
constexpr int PRE4N = KB4N + VB4N + QA4N;

// ---- smem layout (bytes) ----
// A: per-warp 3KB TRIPLE buffer of 1KB granules (loop1: single K stile; loop2: V step)
// B: per-warp fp16 P stash uint32[16][36] = 2304B; reused as fp32 V-partials [16][32]
constexpr uint32_t A_OFF   = 0;                     // 8 * 3072 = 24576
constexpr uint32_t AW_SZ   = 3072;
constexpr uint32_t B_OFF   = 24576;
constexpr uint32_t STASH_W = 2304;
constexpr uint32_t RS_OFF  = B_OFF + 8 * STASH_W;   // 43008
constexpr uint32_t INV_OFF = RS_OFF + 512;          // 43520
constexpr uint32_t SMEM_BYTES = INV_OFF + 64;       // 43584  (x4 = 174KB <= 228KB)

__device__ __forceinline__ uint32_t s2u(const void* p) {
    uint32_t a;
    asm("{ .reg .u64 t; cvta.to.shared.u64 t, %1; cvt.u32.u64 %0, t; }" : "=r"(a) : "l"(p));
    return a;
}
__device__ __forceinline__ void cp16(uint32_t dst, const void* src) {
    asm volatile("cp.async.cg.shared.global [%0], [%1], 16;" :: "r"(dst), "l"(src) : "memory");
}
__device__ __forceinline__ void cpcommit() { asm volatile("cp.async.commit_group;" ::: "memory"); }
__device__ __forceinline__ void cpwait0()  { asm volatile("cp.async.wait_group 0;" ::: "memory"); }
__device__ __forceinline__ void cpwait1()  { asm volatile("cp.async.wait_group 1;" ::: "memory"); }
__device__ __forceinline__ void cpwait2()  { asm volatile("cp.async.wait_group 2;" ::: "memory"); }

__device__ __forceinline__ uint32_t h2(float x, float y) {
    __half2 v = __floats2half2_rn(x, y);
    return *(uint32_t*)&v;
}

__device__ __forceinline__ void mma_f16(float* c, const uint32_t* a, uint32_t b0, uint32_t b1) {
    asm volatile(
        "mma.sync.aligned.m16n8k16.row.col.f32.f16.f16.f32 "
        "{%0,%1,%2,%3},{%4,%5,%6,%7},{%8,%9},{%0,%1,%2,%3};\n"
        : "+f"(c[0]), "+f"(c[1]), "+f"(c[2]), "+f"(c[3])
        : "r"(a[0]), "r"(a[1]), "r"(a[2]), "r"(a[3]), "r"(b0), "r"(b1));
}

// ---------------- prepack (unchanged) ----------------
__global__ void __launch_bounds__(256) prepack(const float* __restrict__ Q,
                                               const float* __restrict__ K,
                                               const float* __restrict__ V) {
    int idx = blockIdx.x * 256 + threadIdx.x;
    int lane = idx & 31, g = (lane >> 2), t = lane & 3;
    if (idx < KB4N) {
        int c = (idx >> 5) & 1, st = (idx >> 6) & 63, bh = idx >> 12;
        int b = bh >> 3, h = bh & 7;
        int s = st * 8 + g;
        const float* kp = K + (((size_t)b * SEQ + s) * NHEAD + h) * HD;
        int ka = (2 * c) * 16 + 2 * t;
        int kb = (2 * c + 1) * 16 + 2 * t;
        d_KB[idx] = make_uint4(h2(kp[ka], kp[ka + 1]), h2(kp[ka + 8], kp[ka + 9]),
                               h2(kp[kb], kp[kb + 1]), h2(kp[kb + 8], kp[kb + 9]));
    } else if (idx < KB4N + VB4N) {
        int i = idx - KB4N;
        int j = (i >> 5) & 3, k2 = (i >> 7) & 3, cq = (i >> 9) & 7, bh = i >> 12;
        int b = bh >> 3, h = bh & 7;
        int s0 = cq * 64 + k2 * 16;
        int d0 = (2 * j) * 8 + g, d1 = (2 * j + 1) * 8 + g;
        const float* vp = V + ((size_t)b * SEQ * NHEAD + h) * HD;
        d_VB[i] = make_uint4(
            h2(vp[(size_t)(s0 + 2 * t) * 512 + d0],     vp[(size_t)(s0 + 2 * t + 1) * 512 + d0]),
            h2(vp[(size_t)(s0 + 2 * t + 8) * 512 + d0], vp[(size_t)(s0 + 2 * t + 9) * 512 + d0]),
            h2(vp[(size_t)(s0 + 2 * t) * 512 + d1],     vp[(size_t)(s0 + 2 * t + 1) * 512 + d1]),
            h2(vp[(size_t)(s0 + 2 * t + 8) * 512 + d1], vp[(size_t)(s0 + 2 * t + 9) * 512 + d1]));
    } else if (idx < PRE4N) {
        int i = idx - KB4N - VB4N;
        int kt = (i >> 5) & 3, rt = (i >> 7) & 31, bh = i >> 12;
        int b = bh >> 3, h = bh & 7;
        int k0 = kt * 16 + 2 * t;
        const float* qp = Q + (((size_t)b * SEQ + rt * 16) * NHEAD + h) * HD;
        d_QA[i] = make_uint4(
            h2(qp[(size_t)g * 512 + k0],           qp[(size_t)g * 512 + k0 + 1]),
            h2(qp[(size_t)(g + 8) * 512 + k0],     qp[(size_t)(g + 8) * 512 + k0 + 1]),
            h2(qp[(size_t)g * 512 + k0 + 8],       qp[(size_t)g * 512 + k0 + 9]),
            h2(qp[(size_t)(g + 8) * 512 + k0 + 8], qp[(size_t)(g + 8) * 512 + k0 + 9]));
    }
}

// ---------------- main ----------------
// CTA: 16 rows x 512 cols. loop1: 8 warps x 8 single-stile pipeline steps.
// loop2: warp = (sh, dh). Triple-buffered 1KB granules. 4 CTAs/SM.
__global__ void __launch_bounds__(256, 4) anomaly_mma(const float* __restrict__ SG,
                                                      float* __restrict__ out) {
    extern __shared__ char sm[];
    const uint32_t smb = s2u(sm);
    float* RS  = (float*)(sm + RS_OFF);
    float* INV = (float*)(sm + INV_OFF);

    const int tid = threadIdx.x, lane = tid & 31, wid = tid >> 5;
    const int g = lane >> 2, t = lane & 3;
    const int mt = blockIdx.x & 31;
    const int bh = blockIdx.x >> 5;
    const int h = bh & 7, b = bh >> 3;
    const int l0 = mt * 16;
    const int cq = wid;

    const uint32_t Aw = smb + A_OFF + wid * AW_SZ;
    char* Awc = sm + A_OFF + wid * AW_SZ;
    uint32_t* stgu = (uint32_t*)(sm + B_OFF + wid * STASH_W);

    const char* srcK = (const char*)d_KB + (size_t)(bh * 64 + cq * 8) * 1024;

    // prologue: issue K stiles 0 and 1 (2 groups in flight)
    #pragma unroll
    for (int ss = 0; ss < 2; ss++) {
        cp16(Aw + ss * 1024 + lane * 16,       srcK + (size_t)ss * 1024 + lane * 16);
        cp16(Aw + ss * 1024 + 512 + lane * 16, srcK + (size_t)ss * 1024 + 512 + lane * 16);
        cpcommit();
    }

    // ---- Q fragments (fp16) ----
    uint32_t qa[4][4];
    {
        const uint4* qp4 = d_QA + ((size_t)(bh * 32 + mt) * 4) * 32 + lane;
        #pragma unroll
        for (int kt = 0; kt < 4; kt++) {
            uint4 v = qp4[kt * 32];
            qa[kt][0] = v.x; qa[kt][1] = v.y; qa[kt][2] = v.z; qa[kt][3] = v.w;
        }
    }

    // ======== loop1: 8 single-stile steps: GEMM1 -> exp -> fp16 stash ========
    float rs0 = 0.f, rs1 = 0.f;
    #pragma unroll
    for (int st = 0; st < 8; st++) {
        if (st < 6) {
            const int stn = st + 2;
            const uint32_t dstb = Aw + (stn % 3) * 1024;
            cp16(dstb + lane * 16,       srcK + (size_t)stn * 1024 + lane * 16);
            cp16(dstb + 512 + lane * 16, srcK + (size_t)stn * 1024 + 512 + lane * 16);
            cpcommit();
        }
        if (st < 6)       cpwait2();
        else if (st == 6) cpwait1();
        else              cpwait0();

        const char* kb = Awc + (st % 3) * 1024;
        uint4 X = *(const uint4*)(kb + lane * 16);        // kt0, kt1
        uint4 Y = *(const uint4*)(kb + 512 + lane * 16);  // kt2, kt3

        float aA[4] = {0.f, 0.f, 0.f, 0.f};
        float aB[4] = {0.f, 0.f, 0.f, 0.f};
        mma_f16(aA, qa[0], X.x, X.y);
        mma_f16(aB, qa[1], X.z, X.w);
        mma_f16(aA, qa[2], Y.x, Y.y);
        mma_f16(aB, qa[3], Y.z, Y.w);

        float p0 = __expf(0.125f * (aA[0] + aB[0]));
        float p1 = __expf(0.125f * (aA[1] + aB[1]));
        float p2 = __expf(0.125f * (aA[2] + aB[2]));
        float p3 = __expf(0.125f * (aA[3] + aB[3]));

        rs0 += p0 + p1;
        rs1 += p2 + p3;

        stgu[g * 36 + st * 4 + t]       = h2(p0, p1);
        stgu[(g + 8) * 36 + st * 4 + t] = h2(p2, p3);
    }

    // ---- loop2 warp roles + V prologue: issue st=0 AND st=1 before barrier ----
    const int sh = wid >> 1;
    const int dh = wid & 1;
    #pragma unroll
    for (int ss = 0; ss < 2; ss++) {
        const char* srcs = (const char*)d_VB +
            ((((size_t)(bh * 8 + 2 * sh + (ss >> 2)) * 4 + (ss & 3)) * 4 + 2 * dh) * 32) * 16;
        const uint32_t dstb = Aw + ss * 1024;
        cp16(dstb + lane * 16,       srcs + lane * 16);
        cp16(dstb + 512 + lane * 16, srcs + 512 + lane * 16);
        cpcommit();
    }

    // ---- rowsums -> inv ----
    rs0 += __shfl_xor_sync(0xffffffffu, rs0, 1);
    rs0 += __shfl_xor_sync(0xffffffffu, rs0, 2);
    rs1 += __shfl_xor_sync(0xffffffffu, rs1, 1);
    rs1 += __shfl_xor_sync(0xffffffffu, rs1, 2);
    if (t == 0) {
        RS[g * 8 + wid]       = rs0;
        RS[(g + 8) * 8 + wid] = rs1;
    }
    __syncthreads();   // publishes stash for cross-warp loop2 reads
    if (tid < 16) {
        float s = 0.f;
        #pragma unroll
        for (int w = 0; w < 8; w++) s += RS[tid * 8 + w];
        INV[tid] = 1.0f / s;
    }
    __syncthreads();
    const float invg  = INV[g];
    const float invg8 = INV[g + 8];

    // ================= loop2: GEMM2 (fp16), triple-buffered V =================
    float vacc[4][4];
    #pragma unroll
    for (int j = 0; j < 4; j++)
        #pragma unroll
        for (int r = 0; r < 4; r++) vacc[j][r] = 0.f;

    #pragma unroll
    for (int st = 0; st < 8; st++) {
        if (st < 6) {
            const int stn = st + 2;
            const char* srcn = (const char*)d_VB +
                ((((size_t)(bh * 8 + 2 * sh + (stn >> 2)) * 4 + (stn & 3)) * 4 + 2 * dh) * 32) * 16;
            const uint32_t dstb = Aw + (stn % 3) * 1024;
            cp16(dstb + lane * 16,       srcn + lane * 16);
            cp16(dstb + 512 + lane * 16, srcn + 512 + lane * 16);
            cpcommit();
        }
        if (st < 6)       cpwait2();
        else if (st == 6) cpwait1();
        else              cpwait0();

        const uint32_t* stq = (const uint32_t*)(sm + B_OFF + (2 * sh + (st >> 2)) * STASH_W);
        const int c0 = (st & 3) * 8;
        uint32_t ua[4];
        ua[0] = stq[g * 36 + c0 + t];
        ua[1] = stq[(g + 8) * 36 + c0 + t];
        ua[2] = stq[g * 36 + c0 + 4 + t];
        ua[3] = stq[(g + 8) * 36 + c0 + 4 + t];

        const char* vb = Awc + (st % 3) * 1024;
        uint4 B0 = *(const uint4*)(vb + lane * 16);
        uint4 B1 = *(const uint4*)(vb + 512 + lane * 16);
        mma_f16(vacc[0], ua, B0.x, B0.y);
        mma_f16(vacc[1], ua, B0.z, B0.w);
        mma_f16(vacc[2], ua, B1.x, B1.y);
        mma_f16(vacc[3], ua, B1.z, B1.w);
    }

    // ---- series write pass: coalesced; unpack fp16 stash ----
    {
        float* ser = out + V_SIZE + ((size_t)bh * 512 + l0) * 512 + cq * 64;
        #pragma unroll
        for (int r = 0; r < 16; r++) {
            uint32_t u = stgu[r * 36 + lane];
            float2 f = __half22float2(*(__half2*)&u);
            const float iv = INV[r];
            __stcs((float2*)(ser + (size_t)r * 512 + lane * 2),
                   make_float2(f.x * iv, f.y * iv));
        }
    }

    // ---- V cross-warp reduction (4 partials per (row,d)) ----
    __syncthreads();   // all warps done reading stashes (loop2 cross-warp + series)
    {
        float* part = (float*)stgu;   // [16 rows][32 d-local] = 2048B <= 2304B
        #pragma unroll
        for (int j = 0; j < 4; j++) {
            part[g * 32 + j * 8 + 2 * t]           = vacc[j][0] * invg;
            part[g * 32 + j * 8 + 2 * t + 1]       = vacc[j][1] * invg;
            part[(g + 8) * 32 + j * 8 + 2 * t]     = vacc[j][2] * invg8;
            part[(g + 8) * 32 + j * 8 + 2 * t + 1] = vacc[j][3] * invg8;
        }
        __syncthreads();
        const int d = tid & 63;
        const int dv = d & 31, wsel = d >> 5;
        #pragma unroll
        for (int it = 0; it < 4; it++) {
            const int row = (tid >> 6) + it * 4;
            float s = 0.f;
            #pragma unroll
            for (int shh = 0; shh < 4; shh++)
                s += ((float*)(sm + B_OFF + (shh * 2 + wsel) * STASH_W))[row * 32 + dv];
            __stcs(out + (((size_t)b * SEQ + l0 + row) * NHEAD + h) * HD + d, s);
        }
    }

    // ---- prior: warp sweeps 128-col chunks, lane*4 contiguous; warp-uniform skip ----
    {
        float amp_ = 0.f, ninv_ = 0.f;
        if (lane < 2) {
            int l = l0 + wid * 2 + lane;
            float x   = SG[((size_t)b * SEQ + l) * NHEAD + h];
            float smv = 1.0f / (1.0f + __expf(-5.0f * x));
            float yf  = smv + 1e-5f;
            float p3  = (float)exp((double)yf * 1.0986122886681098);
            float sig = p3 - 1.0f;
            amp_  = 0.3989422804014327f / sig;
            ninv_ = -1.0f / (2.0f * sig * sig);
        }
        float* priorBase = out + V_SIZE + SER_SIZE + ((size_t)bh * 512 + l0) * 512;
        #pragma unroll
        for (int rr = 0; rr < 2; rr++) {
            const float amp  = __shfl_sync(0xffffffffu, amp_, rr);
            const float ninv = __shfl_sync(0xffffffffu, ninv_, rr);
            const int l = l0 + wid * 2 + rr;
            float* pp = priorBase + (size_t)(wid * 2 + rr) * 512;
            #pragma unroll
            for (int j = 0; j < 4; j++) {
                const int c0 = j * 128;
                int dhh = l - c0, dll = l - (c0 + 127);
                int admin = (dll <= 0 && dhh >= 0) ? 0 : min(abs(dll), abs(dhh));
                float* dst = pp + c0 + lane * 4;
                if (ninv * (float)(admin * admin) < -87.0f) {
                    __stcs((float4*)dst, make_float4(0.f, 0.f, 0.f, 0.f));
                } else {
                    const int s = c0 + lane * 4;
                    float d0 = (float)(l - s);
                    float d1 = (float)(l - (s + 1));
                    float d2 = (float)(l - (s + 2));
                    float d3 = (float)(l - (s + 3));
                    float4 o;
                    o.x = amp * __expf(ninv * d0 * d0);
                    o.y = amp * __expf(ninv * d1 * d1);
                    o.z = amp * __expf(ninv * d2 * d2);
                    o.w = amp * __expf(ninv * d3 * d3);
                    __stcs((float4*)dst, o);
                }
            }
        }
    }
}

extern "C" void kernel_launch(void* const* d_in, const int* in_sizes, int n_in,
                              void* d_out, int out_size) {
    (void)in_sizes; (void)n_in; (void)out_size;
    const float* q  = (const float*)d_in[0];
    const float* k  = (const float*)d_in[1];
    const float* v  = (const float*)d_in[2];
    const float* sg = (const float*)d_in[3];
    float* out = (float*)d_out;

    cudaFuncSetAttribute(anomaly_mma, cudaFuncAttributeMaxDynamicSharedMemorySize,
                         (int)SMEM_BYTES);

    prepack<<<PRE4N / 256, 256>>>(q, k, v);
    anomaly_mma<<<NBATCH * NHEAD * 32, 256, SMEM_BYTES>>>(sg, out);
}